// round 2
// baseline (speedup 1.0000x reference)
#include <cuda_runtime.h>
#include <math.h>

#define BB 2
#define SS 2048
#define DM 1024
#define NH 16
#define DK 64
#define NR (BB*SS)          // 4096 rows
#define OUT_ELEMS (NR*DM)               // 4194304
#define ATTN_ELEMS (BB*NH*SS*SS)        // 134217728

// ---- scratch (device globals; no allocation allowed) ----
__device__ float g_q[NR*DM];
__device__ float g_k[NR*DM];
__device__ float g_v[NR*DM];
__device__ float g_ao[NR*DM];
__device__ float g_m[BB*NH*SS];
__device__ float g_l[BB*NH*SS];

// ============================================================
// SGEMM: C[M,N] = A[M,K] @ W[K,N] + bias ; 128x128x8, 256 thr
// asel: 0 = A_ext, 1 = g_ao       csel: 0 = C_ext, 1=g_q, 2=g_k, 3=g_v
// ============================================================
__global__ __launch_bounds__(256) void sgemm_bias(
    const float* __restrict__ A_ext, int asel,
    const float* __restrict__ W, const float* __restrict__ bias,
    float* __restrict__ C_ext, int csel,
    int M, int N, int K)
{
    const float* A = (asel == 0) ? A_ext : g_ao;
    float* C = (csel == 0) ? C_ext : (csel == 1 ? g_q : (csel == 2 ? g_k : g_v));

    __shared__ float As[8][128];
    __shared__ float Bs[8][128];

    int tid = threadIdx.x;
    int row0 = blockIdx.y * 128;
    int col0 = blockIdx.x * 128;
    int ty = tid >> 4, tx = tid & 15;

    float acc[8][8];
#pragma unroll
    for (int i = 0; i < 8; i++)
#pragma unroll
        for (int j = 0; j < 8; j++) acc[i][j] = 0.f;

    int ar = tid >> 1, ak = (tid & 1) * 4;
    int br = tid >> 5, bc = (tid & 31) * 4;

    for (int k0 = 0; k0 < K; k0 += 8) {
        float4 av = *(const float4*)&A[(size_t)(row0 + ar) * K + k0 + ak];
        As[ak + 0][ar] = av.x; As[ak + 1][ar] = av.y;
        As[ak + 2][ar] = av.z; As[ak + 3][ar] = av.w;
        *(float4*)&Bs[br][bc] = *(const float4*)&W[(size_t)(k0 + br) * N + col0 + bc];
        __syncthreads();
#pragma unroll
        for (int k = 0; k < 8; k++) {
            float a[8], b[8];
#pragma unroll
            for (int i = 0; i < 8; i++) a[i] = As[k][ty * 8 + i];
#pragma unroll
            for (int j = 0; j < 8; j++) b[j] = Bs[k][tx * 8 + j];
#pragma unroll
            for (int i = 0; i < 8; i++)
#pragma unroll
                for (int j = 0; j < 8; j++)
                    acc[i][j] = fmaf(a[i], b[j], acc[i][j]);
        }
        __syncthreads();
    }
#pragma unroll
    for (int i = 0; i < 8; i++) {
        int r = row0 + ty * 8 + i;
#pragma unroll
        for (int j = 0; j < 8; j += 4) {
            int c = col0 + tx * 8 + j;
            float4 o;
            o.x = acc[i][j + 0] + bias[c + 0];
            o.y = acc[i][j + 1] + bias[c + 1];
            o.z = acc[i][j + 2] + bias[c + 2];
            o.w = acc[i][j + 3] + bias[c + 3];
            *(float4*)&C[(size_t)r * N + c] = o;
        }
    }
}

// ============================================================
// Flash attention fwd: per (b,h,q-block of 64), key tiles of 32
// 256 threads: tx=0..15 (cols), ty=0..15 (rows, 4 rows each)
// Stores g_ao (pre-projection, [B,S,H*dk]) and per-row m,l.
// ============================================================
__global__ __launch_bounds__(256) void flash_fwd(const int* __restrict__ token_ids)
{
    __shared__ float Qs[64][65];   // [d][q-row]   (scalar access only)
    __shared__ float Ks[64][33];   // [d][kv]      (scalar access only)
    __shared__ float Vs[32][68];   // [kv][d] stride 68 -> float4-aligned
    __shared__ float Ps[64][33];   // [q-row][kv]  (scalar access only)
    __shared__ float sm_m[64], sm_l[64];
    __shared__ int   padf[32];

    int qb = blockIdx.x, h = blockIdx.y, b = blockIdx.z;
    int q0 = qb * 64;
    int tid = threadIdx.x;
    int tx = tid & 15, ty = tid >> 4;

    // load Q tile (transposed into [d][r])
    {
        int r = tid >> 2;
        int d0 = (tid & 3) * 16;
        const float* qp = &g_q[(size_t)(b * SS + q0 + r) * DM + h * DK + d0];
#pragma unroll
        for (int i = 0; i < 16; i += 4) {
            float4 v4 = *(const float4*)(qp + i);
            Qs[d0 + i + 0][r] = v4.x; Qs[d0 + i + 1][r] = v4.y;
            Qs[d0 + i + 2][r] = v4.z; Qs[d0 + i + 3][r] = v4.w;
        }
    }
    if (tid < 64) { sm_m[tid] = -INFINITY; sm_l[tid] = 0.f; }

    float acc[4][4];
#pragma unroll
    for (int i = 0; i < 4; i++)
#pragma unroll
        for (int j = 0; j < 4; j++) acc[i][j] = 0.f;

    int kb_max = (q0 + 63) / 32;   // inclusive
    for (int kb = 0; kb <= kb_max; kb++) {
        int kv0 = kb * 32;
        {
            int c = tid >> 3;           // 0..31
            int d0 = (tid & 7) * 8;
            const float* kp = &g_k[(size_t)(b * SS + kv0 + c) * DM + h * DK + d0];
            const float* vp = &g_v[(size_t)(b * SS + kv0 + c) * DM + h * DK + d0];
            float4 ka = *(const float4*)kp;
            float4 kb4 = *(const float4*)(kp + 4);
            Ks[d0 + 0][c] = ka.x;  Ks[d0 + 1][c] = ka.y;
            Ks[d0 + 2][c] = ka.z;  Ks[d0 + 3][c] = ka.w;
            Ks[d0 + 4][c] = kb4.x; Ks[d0 + 5][c] = kb4.y;
            Ks[d0 + 6][c] = kb4.z; Ks[d0 + 7][c] = kb4.w;
            *(float4*)&Vs[c][d0]     = *(const float4*)vp;
            *(float4*)&Vs[c][d0 + 4] = *(const float4*)(vp + 4);
        }
        if (tid < 32) padf[tid] = (token_ids[b * SS + kv0 + tid] == 0);
        __syncthreads();

        // S = Q @ K^T  (each thread: 4 rows x 2 cols)
        float s[4][2];
#pragma unroll
        for (int i = 0; i < 4; i++) { s[i][0] = 0.f; s[i][1] = 0.f; }
#pragma unroll
        for (int kk = 0; kk < 64; kk++) {
            float qv[4];
#pragma unroll
            for (int i = 0; i < 4; i++) qv[i] = Qs[kk][ty * 4 + i];
            float k0v = Ks[kk][tx * 2 + 0];
            float k1v = Ks[kk][tx * 2 + 1];
#pragma unroll
            for (int i = 0; i < 4; i++) {
                s[i][0] = fmaf(qv[i], k0v, s[i][0]);
                s[i][1] = fmaf(qv[i], k1v, s[i][1]);
            }
        }
        // scale + mask
#pragma unroll
        for (int i = 0; i < 4; i++) {
            int qi = q0 + ty * 4 + i;
#pragma unroll
            for (int j = 0; j < 2; j++) {
                int ki = kv0 + tx * 2 + j;
                float v = s[i][j] * 0.125f;
                if (ki > qi || padf[tx * 2 + j]) v = -1e9f;
                s[i][j] = v;
            }
        }
        // per-row max across the 16 tx lanes
        float rmax[4];
#pragma unroll
        for (int i = 0; i < 4; i++) rmax[i] = fmaxf(s[i][0], s[i][1]);
#pragma unroll
        for (int off = 8; off; off >>= 1)
#pragma unroll
            for (int i = 0; i < 4; i++)
                rmax[i] = fmaxf(rmax[i], __shfl_xor_sync(0xffffffffu, rmax[i], off));

        // online softmax update
#pragma unroll
        for (int i = 0; i < 4; i++) {
            int r = ty * 4 + i;
            float m_old = sm_m[r];
            float m_new = fmaxf(m_old, rmax[i]);
            float p0 = __expf(s[i][0] - m_new);
            float p1 = __expf(s[i][1] - m_new);
            float rs = p0 + p1;
#pragma unroll
            for (int off = 8; off; off >>= 1)
                rs += __shfl_xor_sync(0xffffffffu, rs, off);
            float sc = __expf(m_old - m_new);
#pragma unroll
            for (int j = 0; j < 4; j++) acc[i][j] *= sc;
            Ps[r][tx * 2 + 0] = p0;
            Ps[r][tx * 2 + 1] = p1;
            if (tx == 0) { sm_m[r] = m_new; sm_l[r] = sm_l[r] * sc + rs; }
        }
        __syncthreads();

        // O += P @ V  (each thread: 4 rows x 4 d-cols)
#pragma unroll
        for (int kk = 0; kk < 32; kk++) {
            float pv[4], vv[4];
#pragma unroll
            for (int i = 0; i < 4; i++) pv[i] = Ps[ty * 4 + i][kk];
#pragma unroll
            for (int j = 0; j < 4; j++) vv[j] = Vs[kk][tx * 4 + j];
#pragma unroll
            for (int i = 0; i < 4; i++)
#pragma unroll
                for (int j = 0; j < 4; j++)
                    acc[i][j] = fmaf(pv[i], vv[j], acc[i][j]);
        }
        __syncthreads();
    }

    // epilogue
#pragma unroll
    for (int i = 0; i < 4; i++) {
        int r = ty * 4 + i;
        int q = q0 + r;
        float m = sm_m[r], l = sm_l[r];
        float4 o;
        if (m > -1e8f) {
            float inv = 1.f / l;
            o.x = acc[i][0] * inv; o.y = acc[i][1] * inv;
            o.z = acc[i][2] * inv; o.w = acc[i][3] * inv;
        } else {
            // reference softmaxes all -1e9 -> uniform over ALL S keys
            float s0 = 0, s1 = 0, s2 = 0, s3 = 0;
            const float* vp = &g_v[(size_t)(b * SS) * DM + h * DK + tx * 4];
            for (int kv = 0; kv < SS; kv++) {
                float4 v4 = *(const float4*)(vp + (size_t)kv * DM);
                s0 += v4.x; s1 += v4.y; s2 += v4.z; s3 += v4.w;
            }
            float inv = 1.f / (float)SS;
            o.x = s0 * inv; o.y = s1 * inv; o.z = s2 * inv; o.w = s3 * inv;
        }
        *(float4*)&g_ao[(size_t)(b * SS + q) * DM + h * DK + tx * 4] = o;
        if (tx == 0) {
            int gi = (b * NH + h) * SS + q;
            bool deg = !(sm_m[r] > -1e8f);
            g_m[gi] = deg ? -1e9f : sm_m[r];
            g_l[gi] = deg ? (float)SS : sm_l[r];
        }
    }
}

// ============================================================
// Optional second pass: write full attention probabilities
// tile 64x64 per block; fully-future tiles need no dot product
// ============================================================
__global__ __launch_bounds__(256) void attn_write(
    const int* __restrict__ token_ids, float* __restrict__ attn)
{
    int kvb = blockIdx.x, qb = blockIdx.y;
    int bh = blockIdx.z;
    int b = bh >> 4, h = bh & 15;
    int q0 = qb * 64, kv0 = kvb * 64;
    int tid = threadIdx.x;
    int tx = tid & 15, ty = tid >> 4;

    if (kv0 > q0 + 63) {
        // entirely causal-masked: exp(-1e9 - m)/l -> 0 unless degenerate row
#pragma unroll
        for (int i = 0; i < 4; i++) {
            int q = q0 + ty * 4 + i;
            int gi = (b * NH + h) * SS + q;
            float m = g_m[gi];
            float val = (m <= -1e8f) ? (1.f / g_l[gi]) : 0.f;
            float4 o = { val, val, val, val };
            *(float4*)&attn[((size_t)(b * NH + h) * SS + q) * SS + kv0 + tx * 4] = o;
        }
        return;
    }

    __shared__ float Qs[64][65];
    __shared__ float Ks2[64][65];
    __shared__ int padf[64];
    {
        int r = tid >> 2;
        int d0 = (tid & 3) * 16;
        const float* qp = &g_q[(size_t)(b * SS + q0 + r) * DM + h * DK + d0];
        const float* kp = &g_k[(size_t)(b * SS + kv0 + r) * DM + h * DK + d0];
#pragma unroll
        for (int i = 0; i < 16; i += 4) {
            float4 v4 = *(const float4*)(qp + i);
            Qs[d0 + i + 0][r] = v4.x; Qs[d0 + i + 1][r] = v4.y;
            Qs[d0 + i + 2][r] = v4.z; Qs[d0 + i + 3][r] = v4.w;
            float4 k4 = *(const float4*)(kp + i);
            Ks2[d0 + i + 0][r] = k4.x; Ks2[d0 + i + 1][r] = k4.y;
            Ks2[d0 + i + 2][r] = k4.z; Ks2[d0 + i + 3][r] = k4.w;
        }
    }
    if (tid < 64) padf[tid] = (token_ids[b * SS + kv0 + tid] == 0);
    __syncthreads();

    float s[4][4];
#pragma unroll
    for (int i = 0; i < 4; i++)
#pragma unroll
        for (int j = 0; j < 4; j++) s[i][j] = 0.f;
#pragma unroll
    for (int kk = 0; kk < 64; kk++) {
        float qv[4], kv_[4];
#pragma unroll
        for (int i = 0; i < 4; i++) qv[i] = Qs[kk][ty * 4 + i];
#pragma unroll
        for (int j = 0; j < 4; j++) kv_[j] = Ks2[kk][tx * 4 + j];
#pragma unroll
        for (int i = 0; i < 4; i++)
#pragma unroll
            for (int j = 0; j < 4; j++)
                s[i][j] = fmaf(qv[i], kv_[j], s[i][j]);
    }
#pragma unroll
    for (int i = 0; i < 4; i++) {
        int q = q0 + ty * 4 + i;
        int gi = (b * NH + h) * SS + q;
        float m = g_m[gi];
        float invl = 1.f / g_l[gi];
        float4 o;
        float ov[4];
#pragma unroll
        for (int j = 0; j < 4; j++) {
            int kvi = kv0 + tx * 4 + j;
            float v = s[i][j] * 0.125f;
            if (kvi > q || padf[tx * 4 + j]) v = -1e9f;
            ov[j] = __expf(v - m) * invl;
        }
        o.x = ov[0]; o.y = ov[1]; o.z = ov[2]; o.w = ov[3];
        *(float4*)&attn[((size_t)(b * NH + h) * SS + q) * SS + kv0 + tx * 4] = o;
    }
}

// ============================================================
extern "C" void kernel_launch(void* const* d_in, const int* in_sizes, int n_in,
                              void* d_out, int out_size)
{
    const float* x  = (const float*)d_in[0];
    const int*  tok = (const int*)d_in[1];
    const float* wq = (const float*)d_in[2];
    const float* bq = (const float*)d_in[3];
    const float* wk = (const float*)d_in[4];
    const float* bk = (const float*)d_in[5];
    const float* wv = (const float*)d_in[6];
    const float* bv = (const float*)d_in[7];
    const float* wo = (const float*)d_in[8];
    const float* bo = (const float*)d_in[9];
    float* out = (float*)d_out;

    dim3 gg(DM / 128, NR / 128);
    sgemm_bias<<<gg, 256>>>(x, 0, wq, bq, nullptr, 1, NR, DM, DM); // -> g_q
    sgemm_bias<<<gg, 256>>>(x, 0, wk, bk, nullptr, 2, NR, DM, DM); // -> g_k
    sgemm_bias<<<gg, 256>>>(x, 0, wv, bv, nullptr, 3, NR, DM, DM); // -> g_v

    flash_fwd<<<dim3(SS / 64, NH, BB), 256>>>(tok);

    bool want_out  = (out_size != ATTN_ELEMS);               // out requested
    bool want_attn = (out_size >= ATTN_ELEMS);               // attn requested
    float* attn_ptr = nullptr;
    if (out_size == ATTN_ELEMS) attn_ptr = out;
    else if (out_size >= OUT_ELEMS + ATTN_ELEMS) attn_ptr = out + OUT_ELEMS;

    if (want_out)
        sgemm_bias<<<gg, 256>>>(nullptr, 1, wo, bo, out, 0, NR, DM, DM);
    if (want_attn && attn_ptr)
        attn_write<<<dim3(SS / 64, SS / 64, BB * NH), 256>>>(tok, attn_ptr);
}

// round 3
// speedup vs baseline: 1.2735x; 1.2735x over previous
#include <cuda_runtime.h>
#include <cuda_bf16.h>
#include <math.h>

#define BB 2
#define SS 2048
#define DM 1024
#define NH 16
#define DK 64
#define NR (BB*SS)          // 4096 rows
#define OUT_ELEMS (NR*DM)               // 4194304
#define ATTN_ELEMS (BB*NH*SS*SS)        // 134217728

// ---- scratch (device globals; no allocation allowed) ----
__device__ float g_q[NR*DM];
__device__ float g_k[NR*DM];
__device__ float g_v[NR*DM];
__device__ float g_ao[NR*DM];
__device__ float g_m[BB*NH*SS];
__device__ float g_l[BB*NH*SS];
// bf16 split operands
__device__ __nv_bfloat16 g_xh[NR*DM],  g_xl[NR*DM];    // input x split
__device__ __nv_bfloat16 g_aoh[NR*DM], g_aol[NR*DM];   // attn output split
__device__ __nv_bfloat16 g_wth[DM*DM], g_wtl[DM*DM];   // current weight, transposed [N][K]

// ============================================================
// split fp32 -> (bf16 hi, bf16 lo).  sel: 0 = x->g_xh/l, 1 = g_ao->g_aoh/l
// ============================================================
__global__ __launch_bounds__(256) void split_bf16(const float* __restrict__ src_ext, int sel)
{
    const float* src = sel ? g_ao : src_ext;
    __nv_bfloat16* hi = sel ? g_aoh : g_xh;
    __nv_bfloat16* lo = sel ? g_aol : g_xl;
    int n = NR * DM;
    for (int i = blockIdx.x * blockDim.x + threadIdx.x; i < n; i += gridDim.x * blockDim.x) {
        float v = src[i];
        __nv_bfloat16 h = __float2bfloat16(v);
        hi[i] = h;
        lo[i] = __float2bfloat16(v - __bfloat162float(h));
    }
}

// ============================================================
// transpose + split: w [K][N] fp32 -> g_wth/g_wtl [N][K] bf16
// ============================================================
__global__ __launch_bounds__(256) void transpose_split(const float* __restrict__ w)
{
    __shared__ float tile[32][33];
    int tx = threadIdx.x, ty = threadIdx.y;       // block 32 x 8
    int n0 = blockIdx.x * 32, k0 = blockIdx.y * 32;
#pragma unroll
    for (int j = 0; j < 32; j += 8)
        tile[ty + j][tx] = w[(size_t)(k0 + ty + j) * DM + n0 + tx];
    __syncthreads();
#pragma unroll
    for (int j = 0; j < 32; j += 8) {
        float v = tile[tx][ty + j];
        __nv_bfloat16 h = __float2bfloat16(v);
        size_t o = (size_t)(n0 + ty + j) * DM + k0 + tx;
        g_wth[o] = h;
        g_wtl[o] = __float2bfloat16(v - __bfloat162float(h));
    }
}

// ============================================================
// split-bf16 tensor-core GEMM: C[M,N] = A @ W + bias
//   A = (Ah+Al) [M][K] bf16 pair, W^T = (g_wth+g_wtl) [N][K]
//   computes Ah*Wh + Ah*Wl + Al*Wh, fp32 accum.
// 128x128x32 tile, 256 thr, warp tile 64x32 (warps 2M x 4N)
// asel: 0 = x split, 1 = ao split.  csel: 0=C_ext, 1=g_q, 2=g_k, 3=g_v
// ============================================================
__device__ __forceinline__ void mma16816(float c[4], const unsigned a[4], const unsigned b[2])
{
    asm volatile(
        "mma.sync.aligned.m16n8k16.row.col.f32.bf16.bf16.f32 "
        "{%0,%1,%2,%3}, {%4,%5,%6,%7}, {%8,%9}, {%0,%1,%2,%3};\n"
        : "+f"(c[0]), "+f"(c[1]), "+f"(c[2]), "+f"(c[3])
        : "r"(a[0]), "r"(a[1]), "r"(a[2]), "r"(a[3]), "r"(b[0]), "r"(b[1]));
}

#define SPAD 40   // smem row stride in bf16 elems (conflict-free, 16B-aligned rows)

__global__ __launch_bounds__(256) void gemm_bf16split(
    int asel, const float* __restrict__ bias, float* __restrict__ C_ext, int csel)
{
    const int M_ = NR, N_ = DM, K_ = DM;
    const __nv_bfloat16* Ah = asel ? g_aoh : g_xh;
    const __nv_bfloat16* Al = asel ? g_aol : g_xl;
    float* C = (csel == 0) ? C_ext : (csel == 1 ? g_q : (csel == 2 ? g_k : g_v));

    __shared__ __nv_bfloat16 Ash[128][SPAD], Asl[128][SPAD];
    __shared__ __nv_bfloat16 Bsh[128][SPAD], Bsl[128][SPAD];

    int tid = threadIdx.x;
    int lane = tid & 31, warp = tid >> 5;
    int wm = warp & 1, wn = warp >> 1;            // 2 x 4 warp grid
    int g = lane >> 2, t = lane & 3;
    int row0 = blockIdx.y * 128, col0 = blockIdx.x * 128;

    float c[4][4][4];                              // [mt][nt][reg]
#pragma unroll
    for (int i = 0; i < 4; i++)
#pragma unroll
        for (int j = 0; j < 4; j++)
#pragma unroll
            for (int r = 0; r < 4; r++) c[i][j][r] = 0.f;

    int lr = tid >> 1;                 // 0..127
    int lko = (tid & 1) * 16;          // 0 / 16

    for (int k0 = 0; k0 < K_; k0 += 32) {
        // A tiles: [row][k]
        {
            const __nv_bfloat16* pa = &Ah[(size_t)(row0 + lr) * K_ + k0 + lko];
            const __nv_bfloat16* pb = &Al[(size_t)(row0 + lr) * K_ + k0 + lko];
            *(uint4*)&Ash[lr][lko]     = *(const uint4*)pa;
            *(uint4*)&Ash[lr][lko + 8] = *(const uint4*)(pa + 8);
            *(uint4*)&Asl[lr][lko]     = *(const uint4*)pb;
            *(uint4*)&Asl[lr][lko + 8] = *(const uint4*)(pb + 8);
        }
        // B tiles: wT [n][k]
        {
            const __nv_bfloat16* pa = &g_wth[(size_t)(col0 + lr) * K_ + k0 + lko];
            const __nv_bfloat16* pb = &g_wtl[(size_t)(col0 + lr) * K_ + k0 + lko];
            *(uint4*)&Bsh[lr][lko]     = *(const uint4*)pa;
            *(uint4*)&Bsh[lr][lko + 8] = *(const uint4*)(pa + 8);
            *(uint4*)&Bsl[lr][lko]     = *(const uint4*)pb;
            *(uint4*)&Bsl[lr][lko + 8] = *(const uint4*)(pb + 8);
        }
        __syncthreads();

#pragma unroll
        for (int kk = 0; kk < 32; kk += 16) {
            unsigned ah[4][4], al[4][4], bh[4][2], bl[4][2];
#pragma unroll
            for (int mt = 0; mt < 4; mt++) {
                int rb = wm * 64 + mt * 16;
                ah[mt][0] = *(const unsigned*)&Ash[rb + g][kk + 2 * t];
                ah[mt][1] = *(const unsigned*)&Ash[rb + g + 8][kk + 2 * t];
                ah[mt][2] = *(const unsigned*)&Ash[rb + g][kk + 2 * t + 8];
                ah[mt][3] = *(const unsigned*)&Ash[rb + g + 8][kk + 2 * t + 8];
                al[mt][0] = *(const unsigned*)&Asl[rb + g][kk + 2 * t];
                al[mt][1] = *(const unsigned*)&Asl[rb + g + 8][kk + 2 * t];
                al[mt][2] = *(const unsigned*)&Asl[rb + g][kk + 2 * t + 8];
                al[mt][3] = *(const unsigned*)&Asl[rb + g + 8][kk + 2 * t + 8];
            }
#pragma unroll
            for (int nt = 0; nt < 4; nt++) {
                int cb = wn * 32 + nt * 8;
                bh[nt][0] = *(const unsigned*)&Bsh[cb + g][kk + 2 * t];
                bh[nt][1] = *(const unsigned*)&Bsh[cb + g][kk + 2 * t + 8];
                bl[nt][0] = *(const unsigned*)&Bsl[cb + g][kk + 2 * t];
                bl[nt][1] = *(const unsigned*)&Bsl[cb + g][kk + 2 * t + 8];
            }
#pragma unroll
            for (int mt = 0; mt < 4; mt++)
#pragma unroll
                for (int nt = 0; nt < 4; nt++) {
                    mma16816(c[mt][nt], ah[mt], bh[nt]);
                    mma16816(c[mt][nt], ah[mt], bl[nt]);
                    mma16816(c[mt][nt], al[mt], bh[nt]);
                }
        }
        __syncthreads();
    }

    // epilogue: bias + store
#pragma unroll
    for (int mt = 0; mt < 4; mt++) {
#pragma unroll
        for (int nt = 0; nt < 4; nt++) {
            int col = col0 + wn * 32 + nt * 8 + 2 * t;
            float bx = bias[col], by = bias[col + 1];
            int r0 = row0 + wm * 64 + mt * 16 + g;
            float2 o0 = { c[mt][nt][0] + bx, c[mt][nt][1] + by };
            float2 o1 = { c[mt][nt][2] + bx, c[mt][nt][3] + by };
            *(float2*)&C[(size_t)r0 * N_ + col] = o0;
            *(float2*)&C[(size_t)(r0 + 8) * N_ + col] = o1;
        }
    }
}

// ============================================================
// Flash attention fwd (unchanged from R2 pass)
// ============================================================
__global__ __launch_bounds__(256) void flash_fwd(const int* __restrict__ token_ids)
{
    __shared__ float Qs[64][65];
    __shared__ float Ks[64][33];
    __shared__ float Vs[32][68];
    __shared__ float Ps[64][33];
    __shared__ float sm_m[64], sm_l[64];
    __shared__ int   padf[32];

    int qb = blockIdx.x, h = blockIdx.y, b = blockIdx.z;
    int q0 = qb * 64;
    int tid = threadIdx.x;
    int tx = tid & 15, ty = tid >> 4;

    {
        int r = tid >> 2;
        int d0 = (tid & 3) * 16;
        const float* qp = &g_q[(size_t)(b * SS + q0 + r) * DM + h * DK + d0];
#pragma unroll
        for (int i = 0; i < 16; i += 4) {
            float4 v4 = *(const float4*)(qp + i);
            Qs[d0 + i + 0][r] = v4.x; Qs[d0 + i + 1][r] = v4.y;
            Qs[d0 + i + 2][r] = v4.z; Qs[d0 + i + 3][r] = v4.w;
        }
    }
    if (tid < 64) { sm_m[tid] = -INFINITY; sm_l[tid] = 0.f; }

    float acc[4][4];
#pragma unroll
    for (int i = 0; i < 4; i++)
#pragma unroll
        for (int j = 0; j < 4; j++) acc[i][j] = 0.f;

    int kb_max = (q0 + 63) / 32;
    for (int kb = 0; kb <= kb_max; kb++) {
        int kv0 = kb * 32;
        {
            int cc = tid >> 3;
            int d0 = (tid & 7) * 8;
            const float* kp = &g_k[(size_t)(b * SS + kv0 + cc) * DM + h * DK + d0];
            const float* vp = &g_v[(size_t)(b * SS + kv0 + cc) * DM + h * DK + d0];
            float4 ka = *(const float4*)kp;
            float4 kb4 = *(const float4*)(kp + 4);
            Ks[d0 + 0][cc] = ka.x;  Ks[d0 + 1][cc] = ka.y;
            Ks[d0 + 2][cc] = ka.z;  Ks[d0 + 3][cc] = ka.w;
            Ks[d0 + 4][cc] = kb4.x; Ks[d0 + 5][cc] = kb4.y;
            Ks[d0 + 6][cc] = kb4.z; Ks[d0 + 7][cc] = kb4.w;
            *(float4*)&Vs[cc][d0]     = *(const float4*)vp;
            *(float4*)&Vs[cc][d0 + 4] = *(const float4*)(vp + 4);
        }
        if (tid < 32) padf[tid] = (token_ids[b * SS + kv0 + tid] == 0);
        __syncthreads();

        float s[4][2];
#pragma unroll
        for (int i = 0; i < 4; i++) { s[i][0] = 0.f; s[i][1] = 0.f; }
#pragma unroll
        for (int kk = 0; kk < 64; kk++) {
            float qv[4];
#pragma unroll
            for (int i = 0; i < 4; i++) qv[i] = Qs[kk][ty * 4 + i];
            float k0v = Ks[kk][tx * 2 + 0];
            float k1v = Ks[kk][tx * 2 + 1];
#pragma unroll
            for (int i = 0; i < 4; i++) {
                s[i][0] = fmaf(qv[i], k0v, s[i][0]);
                s[i][1] = fmaf(qv[i], k1v, s[i][1]);
            }
        }
#pragma unroll
        for (int i = 0; i < 4; i++) {
            int qi = q0 + ty * 4 + i;
#pragma unroll
            for (int j = 0; j < 2; j++) {
                int ki = kv0 + tx * 2 + j;
                float v = s[i][j] * 0.125f;
                if (ki > qi || padf[tx * 2 + j]) v = -1e9f;
                s[i][j] = v;
            }
        }
        float rmax[4];
#pragma unroll
        for (int i = 0; i < 4; i++) rmax[i] = fmaxf(s[i][0], s[i][1]);
#pragma unroll
        for (int off = 8; off; off >>= 1)
#pragma unroll
            for (int i = 0; i < 4; i++)
                rmax[i] = fmaxf(rmax[i], __shfl_xor_sync(0xffffffffu, rmax[i], off));

#pragma unroll
        for (int i = 0; i < 4; i++) {
            int r = ty * 4 + i;
            float m_old = sm_m[r];
            float m_new = fmaxf(m_old, rmax[i]);
            float p0 = __expf(s[i][0] - m_new);
            float p1 = __expf(s[i][1] - m_new);
            float rs = p0 + p1;
#pragma unroll
            for (int off = 8; off; off >>= 1)
                rs += __shfl_xor_sync(0xffffffffu, rs, off);
            float sc = __expf(m_old - m_new);
#pragma unroll
            for (int j = 0; j < 4; j++) acc[i][j] *= sc;
            Ps[r][tx * 2 + 0] = p0;
            Ps[r][tx * 2 + 1] = p1;
            if (tx == 0) { sm_m[r] = m_new; sm_l[r] = sm_l[r] * sc + rs; }
        }
        __syncthreads();

#pragma unroll
        for (int kk = 0; kk < 32; kk++) {
            float pv[4], vv[4];
#pragma unroll
            for (int i = 0; i < 4; i++) pv[i] = Ps[ty * 4 + i][kk];
#pragma unroll
            for (int j = 0; j < 4; j++) vv[j] = Vs[kk][tx * 4 + j];
#pragma unroll
            for (int i = 0; i < 4; i++)
#pragma unroll
                for (int j = 0; j < 4; j++)
                    acc[i][j] = fmaf(pv[i], vv[j], acc[i][j]);
        }
        __syncthreads();
    }

#pragma unroll
    for (int i = 0; i < 4; i++) {
        int r = ty * 4 + i;
        int q = q0 + r;
        float m = sm_m[r], l = sm_l[r];
        float4 o;
        if (m > -1e8f) {
            float inv = 1.f / l;
            o.x = acc[i][0] * inv; o.y = acc[i][1] * inv;
            o.z = acc[i][2] * inv; o.w = acc[i][3] * inv;
        } else {
            float s0 = 0, s1 = 0, s2 = 0, s3 = 0;
            const float* vp = &g_v[(size_t)(b * SS) * DM + h * DK + tx * 4];
            for (int kv = 0; kv < SS; kv++) {
                float4 v4 = *(const float4*)(vp + (size_t)kv * DM);
                s0 += v4.x; s1 += v4.y; s2 += v4.z; s3 += v4.w;
            }
            float inv = 1.f / (float)SS;
            o.x = s0 * inv; o.y = s1 * inv; o.z = s2 * inv; o.w = s3 * inv;
        }
        *(float4*)&g_ao[(size_t)(b * SS + q) * DM + h * DK + tx * 4] = o;
        if (tx == 0) {
            int gi = (b * NH + h) * SS + q;
            bool deg = !(sm_m[r] > -1e8f);
            g_m[gi] = deg ? -1e9f : sm_m[r];
            g_l[gi] = deg ? (float)SS : sm_l[r];
        }
    }
}

// ============================================================
// Optional second pass: full attention probabilities (unchanged)
// ============================================================
__global__ __launch_bounds__(256) void attn_write(
    const int* __restrict__ token_ids, float* __restrict__ attn)
{
    int kvb = blockIdx.x, qb = blockIdx.y;
    int bh = blockIdx.z;
    int b = bh >> 4, h = bh & 15;
    int q0 = qb * 64, kv0 = kvb * 64;
    int tid = threadIdx.x;
    int tx = tid & 15, ty = tid >> 4;

    if (kv0 > q0 + 63) {
#pragma unroll
        for (int i = 0; i < 4; i++) {
            int q = q0 + ty * 4 + i;
            int gi = (b * NH + h) * SS + q;
            float m = g_m[gi];
            float val = (m <= -1e8f) ? (1.f / g_l[gi]) : 0.f;
            float4 o = { val, val, val, val };
            *(float4*)&attn[((size_t)(b * NH + h) * SS + q) * SS + kv0 + tx * 4] = o;
        }
        return;
    }

    __shared__ float Qs[64][65];
    __shared__ float Ks2[64][65];
    __shared__ int padf[64];
    {
        int r = tid >> 2;
        int d0 = (tid & 3) * 16;
        const float* qp = &g_q[(size_t)(b * SS + q0 + r) * DM + h * DK + d0];
        const float* kp = &g_k[(size_t)(b * SS + kv0 + r) * DM + h * DK + d0];
#pragma unroll
        for (int i = 0; i < 16; i += 4) {
            float4 v4 = *(const float4*)(qp + i);
            Qs[d0 + i + 0][r] = v4.x; Qs[d0 + i + 1][r] = v4.y;
            Qs[d0 + i + 2][r] = v4.z; Qs[d0 + i + 3][r] = v4.w;
            float4 k4 = *(const float4*)(kp + i);
            Ks2[d0 + i + 0][r] = k4.x; Ks2[d0 + i + 1][r] = k4.y;
            Ks2[d0 + i + 2][r] = k4.z; Ks2[d0 + i + 3][r] = k4.w;
        }
    }
    if (tid < 64) padf[tid] = (token_ids[b * SS + kv0 + tid] == 0);
    __syncthreads();

    float s[4][4];
#pragma unroll
    for (int i = 0; i < 4; i++)
#pragma unroll
        for (int j = 0; j < 4; j++) s[i][j] = 0.f;
#pragma unroll
    for (int kk = 0; kk < 64; kk++) {
        float qv[4], kv_[4];
#pragma unroll
        for (int i = 0; i < 4; i++) qv[i] = Qs[kk][ty * 4 + i];
#pragma unroll
        for (int j = 0; j < 4; j++) kv_[j] = Ks2[kk][tx * 4 + j];
#pragma unroll
        for (int i = 0; i < 4; i++)
#pragma unroll
            for (int j = 0; j < 4; j++)
                s[i][j] = fmaf(qv[i], kv_[j], s[i][j]);
    }
#pragma unroll
    for (int i = 0; i < 4; i++) {
        int q = q0 + ty * 4 + i;
        int gi = (b * NH + h) * SS + q;
        float m = g_m[gi];
        float invl = 1.f / g_l[gi];
        float4 o;
        float ov[4];
#pragma unroll
        for (int j = 0; j < 4; j++) {
            int kvi = kv0 + tx * 4 + j;
            float v = s[i][j] * 0.125f;
            if (kvi > q || padf[tx * 4 + j]) v = -1e9f;
            ov[j] = __expf(v - m) * invl;
        }
        o.x = ov[0]; o.y = ov[1]; o.z = ov[2]; o.w = ov[3];
        *(float4*)&attn[((size_t)(b * NH + h) * SS + q) * SS + kv0 + tx * 4] = o;
    }
}

// ============================================================
extern "C" void kernel_launch(void* const* d_in, const int* in_sizes, int n_in,
                              void* d_out, int out_size)
{
    const float* x  = (const float*)d_in[0];
    const int*  tok = (const int*)d_in[1];
    const float* wq = (const float*)d_in[2];
    const float* bq = (const float*)d_in[3];
    const float* wk = (const float*)d_in[4];
    const float* bk = (const float*)d_in[5];
    const float* wv = (const float*)d_in[6];
    const float* bv = (const float*)d_in[7];
    const float* wo = (const float*)d_in[8];
    const float* bo = (const float*)d_in[9];
    float* out = (float*)d_out;

    dim3 gT(DM / 32, DM / 32), bT(32, 8);
    dim3 gG(DM / 128, NR / 128);

    split_bf16<<<1024, 256>>>(x, 0);                   // x -> g_xh/g_xl

    transpose_split<<<gT, bT>>>(wq);
    gemm_bf16split<<<gG, 256>>>(0, bq, nullptr, 1);    // -> g_q
    transpose_split<<<gT, bT>>>(wk);
    gemm_bf16split<<<gG, 256>>>(0, bk, nullptr, 2);    // -> g_k
    transpose_split<<<gT, bT>>>(wv);
    gemm_bf16split<<<gG, 256>>>(0, bv, nullptr, 3);    // -> g_v

    flash_fwd<<<dim3(SS / 64, NH, BB), 256>>>(tok);

    bool want_out  = (out_size != ATTN_ELEMS);
    bool want_attn = (out_size >= ATTN_ELEMS);
    float* attn_ptr = nullptr;
    if (out_size == ATTN_ELEMS) attn_ptr = out;
    else if (out_size >= OUT_ELEMS + ATTN_ELEMS) attn_ptr = out + OUT_ELEMS;

    if (want_out) {
        split_bf16<<<1024, 256>>>(nullptr, 1);         // g_ao -> g_aoh/g_aol
        transpose_split<<<gT, bT>>>(wo);
        gemm_bf16split<<<gG, 256>>>(1, bo, out, 0);    // -> out
    }
    if (want_attn && attn_ptr)
        attn_write<<<dim3(SS / 64, SS / 64, BB * NH), 256>>>(tok, attn_ptr);
}

// round 4
// speedup vs baseline: 1.5781x; 1.2392x over previous
#include <cuda_runtime.h>
#include <cuda_bf16.h>
#include <math.h>

#define BB 2
#define SS 2048
#define DM 1024
#define NH 16
#define DK 64
#define NR (BB*SS)          // 4096 rows
#define OUT_ELEMS (NR*DM)               // 4194304
#define ATTN_ELEMS (BB*NH*SS*SS)        // 134217728

// ---- scratch (device globals; no allocation allowed) ----
__device__ float g_q[NR*DM];
__device__ float g_k[NR*DM];
__device__ float g_v[NR*DM];
__device__ float g_ao[NR*DM];
__device__ float g_m[BB*NH*SS];
__device__ float g_l[BB*NH*SS];
// bf16 split operands
__device__ __nv_bfloat16 g_xh[NR*DM],  g_xl[NR*DM];    // input x split
__device__ __nv_bfloat16 g_aoh[NR*DM], g_aol[NR*DM];   // attn output split
__device__ __nv_bfloat16 g_wth[DM*DM], g_wtl[DM*DM];   // current weight, transposed [N][K]

__device__ __forceinline__ void mma16816(float c[4], const unsigned a[4], const unsigned b[2])
{
    asm volatile(
        "mma.sync.aligned.m16n8k16.row.col.f32.bf16.bf16.f32 "
        "{%0,%1,%2,%3}, {%4,%5,%6,%7}, {%8,%9}, {%0,%1,%2,%3};\n"
        : "+f"(c[0]), "+f"(c[1]), "+f"(c[2]), "+f"(c[3])
        : "r"(a[0]), "r"(a[1]), "r"(a[2]), "r"(a[3]), "r"(b[0]), "r"(b[1]));
}

__device__ __forceinline__ unsigned pack_bf2(__nv_bfloat16 a, __nv_bfloat16 b)
{
    return (unsigned)__bfloat16_as_ushort(a) | ((unsigned)__bfloat16_as_ushort(b) << 16);
}

// ============================================================
// split fp32 -> (bf16 hi, bf16 lo).  sel: 0 = x, 1 = g_ao
// ============================================================
__global__ __launch_bounds__(256) void split_bf16(const float* __restrict__ src_ext, int sel)
{
    const float* src = sel ? g_ao : src_ext;
    __nv_bfloat16* hi = sel ? g_aoh : g_xh;
    __nv_bfloat16* lo = sel ? g_aol : g_xl;
    int n = NR * DM;
    for (int i = blockIdx.x * blockDim.x + threadIdx.x; i < n; i += gridDim.x * blockDim.x) {
        float v = src[i];
        __nv_bfloat16 h = __float2bfloat16(v);
        hi[i] = h;
        lo[i] = __float2bfloat16(v - __bfloat162float(h));
    }
}

// ============================================================
// transpose + split: w [K][N] fp32 -> g_wth/g_wtl [N][K] bf16
// ============================================================
__global__ __launch_bounds__(256) void transpose_split(const float* __restrict__ w)
{
    __shared__ float tile[32][33];
    int tx = threadIdx.x, ty = threadIdx.y;       // block 32 x 8
    int n0 = blockIdx.x * 32, k0 = blockIdx.y * 32;
#pragma unroll
    for (int j = 0; j < 32; j += 8)
        tile[ty + j][tx] = w[(size_t)(k0 + ty + j) * DM + n0 + tx];
    __syncthreads();
#pragma unroll
    for (int j = 0; j < 32; j += 8) {
        float v = tile[tx][ty + j];
        __nv_bfloat16 h = __float2bfloat16(v);
        size_t o = (size_t)(n0 + ty + j) * DM + k0 + tx;
        g_wth[o] = h;
        g_wtl[o] = __float2bfloat16(v - __bfloat162float(h));
    }
}

// ============================================================
// split-bf16 tensor-core GEMM (unchanged from R3)
// ============================================================
#define SPAD 40

__global__ __launch_bounds__(256) void gemm_bf16split(
    int asel, const float* __restrict__ bias, float* __restrict__ C_ext, int csel)
{
    const int N_ = DM, K_ = DM;
    const __nv_bfloat16* Ah = asel ? g_aoh : g_xh;
    const __nv_bfloat16* Al = asel ? g_aol : g_xl;
    float* C = (csel == 0) ? C_ext : (csel == 1 ? g_q : (csel == 2 ? g_k : g_v));

    __shared__ __nv_bfloat16 Ash[128][SPAD], Asl[128][SPAD];
    __shared__ __nv_bfloat16 Bsh[128][SPAD], Bsl[128][SPAD];

    int tid = threadIdx.x;
    int lane = tid & 31, warp = tid >> 5;
    int wm = warp & 1, wn = warp >> 1;
    int g = lane >> 2, t = lane & 3;
    int row0 = blockIdx.y * 128, col0 = blockIdx.x * 128;

    float c[4][4][4];
#pragma unroll
    for (int i = 0; i < 4; i++)
#pragma unroll
        for (int j = 0; j < 4; j++)
#pragma unroll
            for (int r = 0; r < 4; r++) c[i][j][r] = 0.f;

    int lr = tid >> 1;
    int lko = (tid & 1) * 16;

    for (int k0 = 0; k0 < K_; k0 += 32) {
        {
            const __nv_bfloat16* pa = &Ah[(size_t)(row0 + lr) * K_ + k0 + lko];
            const __nv_bfloat16* pb = &Al[(size_t)(row0 + lr) * K_ + k0 + lko];
            *(uint4*)&Ash[lr][lko]     = *(const uint4*)pa;
            *(uint4*)&Ash[lr][lko + 8] = *(const uint4*)(pa + 8);
            *(uint4*)&Asl[lr][lko]     = *(const uint4*)pb;
            *(uint4*)&Asl[lr][lko + 8] = *(const uint4*)(pb + 8);
        }
        {
            const __nv_bfloat16* pa = &g_wth[(size_t)(col0 + lr) * K_ + k0 + lko];
            const __nv_bfloat16* pb = &g_wtl[(size_t)(col0 + lr) * K_ + k0 + lko];
            *(uint4*)&Bsh[lr][lko]     = *(const uint4*)pa;
            *(uint4*)&Bsh[lr][lko + 8] = *(const uint4*)(pa + 8);
            *(uint4*)&Bsl[lr][lko]     = *(const uint4*)pb;
            *(uint4*)&Bsl[lr][lko + 8] = *(const uint4*)(pb + 8);
        }
        __syncthreads();

#pragma unroll
        for (int kk = 0; kk < 32; kk += 16) {
            unsigned ah[4][4], al[4][4], bh[4][2], bl[4][2];
#pragma unroll
            for (int mt = 0; mt < 4; mt++) {
                int rb = wm * 64 + mt * 16;
                ah[mt][0] = *(const unsigned*)&Ash[rb + g][kk + 2 * t];
                ah[mt][1] = *(const unsigned*)&Ash[rb + g + 8][kk + 2 * t];
                ah[mt][2] = *(const unsigned*)&Ash[rb + g][kk + 2 * t + 8];
                ah[mt][3] = *(const unsigned*)&Ash[rb + g + 8][kk + 2 * t + 8];
                al[mt][0] = *(const unsigned*)&Asl[rb + g][kk + 2 * t];
                al[mt][1] = *(const unsigned*)&Asl[rb + g + 8][kk + 2 * t];
                al[mt][2] = *(const unsigned*)&Asl[rb + g][kk + 2 * t + 8];
                al[mt][3] = *(const unsigned*)&Asl[rb + g + 8][kk + 2 * t + 8];
            }
#pragma unroll
            for (int nt = 0; nt < 4; nt++) {
                int cb = wn * 32 + nt * 8;
                bh[nt][0] = *(const unsigned*)&Bsh[cb + g][kk + 2 * t];
                bh[nt][1] = *(const unsigned*)&Bsh[cb + g][kk + 2 * t + 8];
                bl[nt][0] = *(const unsigned*)&Bsl[cb + g][kk + 2 * t];
                bl[nt][1] = *(const unsigned*)&Bsl[cb + g][kk + 2 * t + 8];
            }
#pragma unroll
            for (int mt = 0; mt < 4; mt++)
#pragma unroll
                for (int nt = 0; nt < 4; nt++) {
                    mma16816(c[mt][nt], ah[mt], bh[nt]);
                    mma16816(c[mt][nt], ah[mt], bl[nt]);
                    mma16816(c[mt][nt], al[mt], bh[nt]);
                }
        }
        __syncthreads();
    }

#pragma unroll
    for (int mt = 0; mt < 4; mt++) {
#pragma unroll
        for (int nt = 0; nt < 4; nt++) {
            int col = col0 + wn * 32 + nt * 8 + 2 * t;
            float bx = bias[col], by = bias[col + 1];
            int r0 = row0 + wm * 64 + mt * 16 + g;
            float2 o0 = { c[mt][nt][0] + bx, c[mt][nt][1] + by };
            float2 o1 = { c[mt][nt][2] + bx, c[mt][nt][3] + by };
            *(float2*)&C[(size_t)r0 * DM + col] = o0;
            *(float2*)&C[(size_t)(r0 + 8) * DM + col] = o1;
        }
    }
}

// ============================================================
// Tensor-core flash attention: BQ=64, BKV=32, 128 thr (4 warps x 16 rows)
// split-bf16 3-term mma for both QK^T and PV; softmax in registers.
// ============================================================
__global__ __launch_bounds__(128) void flash_tc(const int* __restrict__ token_ids)
{
    __shared__ __nv_bfloat16 Qh[64][72], Ql[64][72];   // [q-row][dk]
    __shared__ __nv_bfloat16 Kh[32][72], Kl[32][72];   // [kv][dk]
    __shared__ __nv_bfloat16 Vth[64][40], Vtl[64][40]; // [dk][kv]
    __shared__ int padf[32];

    int qb = blockIdx.x, h = blockIdx.y, b = blockIdx.z;
    int q0 = qb * 64;
    int tid = threadIdx.x, lane = tid & 31, w = tid >> 5;
    int g = lane >> 2, t = lane & 3;

    // load Q (64x64 fp32 -> bf16 hi/lo)
    {
        int r = tid >> 1, c0 = (tid & 1) * 32;
        const float* qp = &g_q[(size_t)(b * SS + q0 + r) * DM + h * DK + c0];
#pragma unroll
        for (int i = 0; i < 32; i += 2) {
            float2 v = *(const float2*)(qp + i);
            __nv_bfloat16 h0 = __float2bfloat16(v.x), h1 = __float2bfloat16(v.y);
            __nv_bfloat16 l0 = __float2bfloat16(v.x - __bfloat162float(h0));
            __nv_bfloat16 l1 = __float2bfloat16(v.y - __bfloat162float(h1));
            *(unsigned*)&Qh[r][c0 + i] = pack_bf2(h0, h1);
            *(unsigned*)&Ql[r][c0 + i] = pack_bf2(l0, l1);
        }
    }

    float o[8][4];
#pragma unroll
    for (int i = 0; i < 8; i++)
#pragma unroll
        for (int j = 0; j < 4; j++) o[i][j] = 0.f;
    float m0 = -INFINITY, m1 = -INFINITY, l0 = 0.f, l1 = 0.f;

    int row0 = q0 + w * 16 + g;
    int row1 = row0 + 8;

    int kb_max = 2 * qb + 1;
    for (int kb = 0; kb <= kb_max; kb++) {
        int kv0 = kb * 32;
        // load K (32x64) and V transposed
        {
            int r = tid >> 2, c0 = (tid & 3) * 16;
            const float* kp = &g_k[(size_t)(b * SS + kv0 + r) * DM + h * DK + c0];
            const float* vp = &g_v[(size_t)(b * SS + kv0 + r) * DM + h * DK + c0];
#pragma unroll
            for (int i = 0; i < 16; i += 2) {
                float2 kv2 = *(const float2*)(kp + i);
                __nv_bfloat16 h0 = __float2bfloat16(kv2.x), h1 = __float2bfloat16(kv2.y);
                __nv_bfloat16 q0b = __float2bfloat16(kv2.x - __bfloat162float(h0));
                __nv_bfloat16 q1b = __float2bfloat16(kv2.y - __bfloat162float(h1));
                *(unsigned*)&Kh[r][c0 + i] = pack_bf2(h0, h1);
                *(unsigned*)&Kl[r][c0 + i] = pack_bf2(q0b, q1b);
                float2 vv2 = *(const float2*)(vp + i);
                __nv_bfloat16 vh0 = __float2bfloat16(vv2.x), vh1 = __float2bfloat16(vv2.y);
                Vth[c0 + i][r] = vh0;
                Vth[c0 + i + 1][r] = vh1;
                Vtl[c0 + i][r] = __float2bfloat16(vv2.x - __bfloat162float(vh0));
                Vtl[c0 + i + 1][r] = __float2bfloat16(vv2.y - __bfloat162float(vh1));
            }
        }
        if (tid < 32) padf[tid] = (token_ids[b * SS + kv0 + tid] == 0);
        __syncthreads();

        // S = Q K^T : per warp 16x32, 4 n-tiles
        float s[4][4];
#pragma unroll
        for (int nt = 0; nt < 4; nt++)
#pragma unroll
            for (int r = 0; r < 4; r++) s[nt][r] = 0.f;

#pragma unroll
        for (int kc = 0; kc < 4; kc++) {
            int kk = kc * 16;
            unsigned aqh[4], aql[4];
            int rb = w * 16;
            aqh[0] = *(const unsigned*)&Qh[rb + g][kk + 2 * t];
            aqh[1] = *(const unsigned*)&Qh[rb + g + 8][kk + 2 * t];
            aqh[2] = *(const unsigned*)&Qh[rb + g][kk + 2 * t + 8];
            aqh[3] = *(const unsigned*)&Qh[rb + g + 8][kk + 2 * t + 8];
            aql[0] = *(const unsigned*)&Ql[rb + g][kk + 2 * t];
            aql[1] = *(const unsigned*)&Ql[rb + g + 8][kk + 2 * t];
            aql[2] = *(const unsigned*)&Ql[rb + g][kk + 2 * t + 8];
            aql[3] = *(const unsigned*)&Ql[rb + g + 8][kk + 2 * t + 8];
#pragma unroll
            for (int nt = 0; nt < 4; nt++) {
                unsigned bh[2], bl[2];
                bh[0] = *(const unsigned*)&Kh[nt * 8 + g][kk + 2 * t];
                bh[1] = *(const unsigned*)&Kh[nt * 8 + g][kk + 2 * t + 8];
                bl[0] = *(const unsigned*)&Kl[nt * 8 + g][kk + 2 * t];
                bl[1] = *(const unsigned*)&Kl[nt * 8 + g][kk + 2 * t + 8];
                mma16816(s[nt], aqh, bh);
                mma16816(s[nt], aqh, bl);
                mma16816(s[nt], aql, bh);
            }
        }

        // scale + mask
#pragma unroll
        for (int nt = 0; nt < 4; nt++) {
            int c0 = nt * 8 + 2 * t;
            int k0i = kv0 + c0, k1i = k0i + 1;
            int p0 = padf[c0], p1 = padf[c0 + 1];
            float v0 = s[nt][0] * 0.125f, v1 = s[nt][1] * 0.125f;
            float v2 = s[nt][2] * 0.125f, v3 = s[nt][3] * 0.125f;
            s[nt][0] = (k0i > row0 || p0) ? -1e9f : v0;
            s[nt][1] = (k1i > row0 || p1) ? -1e9f : v1;
            s[nt][2] = (k0i > row1 || p0) ? -1e9f : v2;
            s[nt][3] = (k1i > row1 || p1) ? -1e9f : v3;
        }

        // row max (within thread then across quad)
        float rmax0 = -INFINITY, rmax1 = -INFINITY;
#pragma unroll
        for (int nt = 0; nt < 4; nt++) {
            rmax0 = fmaxf(rmax0, fmaxf(s[nt][0], s[nt][1]));
            rmax1 = fmaxf(rmax1, fmaxf(s[nt][2], s[nt][3]));
        }
#pragma unroll
        for (int off = 1; off <= 2; off <<= 1) {
            rmax0 = fmaxf(rmax0, __shfl_xor_sync(0xffffffffu, rmax0, off));
            rmax1 = fmaxf(rmax1, __shfl_xor_sync(0xffffffffu, rmax1, off));
        }
        float mn0 = fmaxf(m0, rmax0), mn1 = fmaxf(m1, rmax1);

        // exponentiate; row sums
        float rs0 = 0.f, rs1 = 0.f;
#pragma unroll
        for (int nt = 0; nt < 4; nt++) {
            s[nt][0] = __expf(s[nt][0] - mn0);
            s[nt][1] = __expf(s[nt][1] - mn0);
            s[nt][2] = __expf(s[nt][2] - mn1);
            s[nt][3] = __expf(s[nt][3] - mn1);
            rs0 += s[nt][0] + s[nt][1];
            rs1 += s[nt][2] + s[nt][3];
        }
#pragma unroll
        for (int off = 1; off <= 2; off <<= 1) {
            rs0 += __shfl_xor_sync(0xffffffffu, rs0, off);
            rs1 += __shfl_xor_sync(0xffffffffu, rs1, off);
        }
        float sc0 = __expf(m0 - mn0), sc1 = __expf(m1 - mn1);
        l0 = l0 * sc0 + rs0;
        l1 = l1 * sc1 + rs1;
        m0 = mn0; m1 = mn1;
#pragma unroll
        for (int ot = 0; ot < 8; ot++) {
            o[ot][0] *= sc0; o[ot][1] *= sc0;
            o[ot][2] *= sc1; o[ot][3] *= sc1;
        }

        // P fragments directly from S regs (C-layout == A-layout identity)
#pragma unroll
        for (int kc = 0; kc < 2; kc++) {
            unsigned ph[4], pl[4];
            {
                int n0i = 2 * kc, n1i = 2 * kc + 1;
                __nv_bfloat16 h00 = __float2bfloat16(s[n0i][0]);
                __nv_bfloat16 h01 = __float2bfloat16(s[n0i][1]);
                __nv_bfloat16 h02 = __float2bfloat16(s[n0i][2]);
                __nv_bfloat16 h03 = __float2bfloat16(s[n0i][3]);
                __nv_bfloat16 h10 = __float2bfloat16(s[n1i][0]);
                __nv_bfloat16 h11 = __float2bfloat16(s[n1i][1]);
                __nv_bfloat16 h12 = __float2bfloat16(s[n1i][2]);
                __nv_bfloat16 h13 = __float2bfloat16(s[n1i][3]);
                ph[0] = pack_bf2(h00, h01);
                ph[1] = pack_bf2(h02, h03);
                ph[2] = pack_bf2(h10, h11);
                ph[3] = pack_bf2(h12, h13);
                pl[0] = pack_bf2(__float2bfloat16(s[n0i][0] - __bfloat162float(h00)),
                                 __float2bfloat16(s[n0i][1] - __bfloat162float(h01)));
                pl[1] = pack_bf2(__float2bfloat16(s[n0i][2] - __bfloat162float(h02)),
                                 __float2bfloat16(s[n0i][3] - __bfloat162float(h03)));
                pl[2] = pack_bf2(__float2bfloat16(s[n1i][0] - __bfloat162float(h10)),
                                 __float2bfloat16(s[n1i][1] - __bfloat162float(h11)));
                pl[3] = pack_bf2(__float2bfloat16(s[n1i][2] - __bfloat162float(h12)),
                                 __float2bfloat16(s[n1i][3] - __bfloat162float(h13)));
            }
            int kk = kc * 16;
#pragma unroll
            for (int ot = 0; ot < 8; ot++) {
                unsigned bvh[2], bvl[2];
                bvh[0] = *(const unsigned*)&Vth[ot * 8 + g][kk + 2 * t];
                bvh[1] = *(const unsigned*)&Vth[ot * 8 + g][kk + 2 * t + 8];
                bvl[0] = *(const unsigned*)&Vtl[ot * 8 + g][kk + 2 * t];
                bvl[1] = *(const unsigned*)&Vtl[ot * 8 + g][kk + 2 * t + 8];
                mma16816(o[ot], ph, bvh);
                mma16816(o[ot], ph, bvl);
                mma16816(o[ot], pl, bvh);
            }
        }
        __syncthreads();
    }

    // epilogue
    bool deg0 = !(m0 > -1e8f);
    bool deg1 = !(m1 > -1e8f);
    float inv0 = deg0 ? 0.f : 1.f / l0;
    float inv1 = deg1 ? 0.f : 1.f / l1;
#pragma unroll
    for (int ot = 0; ot < 8; ot++) {
        int col = h * DK + ot * 8 + 2 * t;
        float2 o0 = { o[ot][0] * inv0, o[ot][1] * inv0 };
        float2 o1 = { o[ot][2] * inv1, o[ot][3] * inv1 };
        if (deg0) {
            float s0 = 0.f, s1 = 0.f;
            const float* vp = &g_v[(size_t)(b * SS) * DM + col];
            for (int kv = 0; kv < SS; kv++) {
                float2 v2 = *(const float2*)(vp + (size_t)kv * DM);
                s0 += v2.x; s1 += v2.y;
            }
            o0.x = s0 / SS; o0.y = s1 / SS;
        }
        if (deg1) {
            float s0 = 0.f, s1 = 0.f;
            const float* vp = &g_v[(size_t)(b * SS) * DM + col];
            for (int kv = 0; kv < SS; kv++) {
                float2 v2 = *(const float2*)(vp + (size_t)kv * DM);
                s0 += v2.x; s1 += v2.y;
            }
            o1.x = s0 / SS; o1.y = s1 / SS;
        }
        *(float2*)&g_ao[(size_t)(b * SS + row0) * DM + col] = o0;
        *(float2*)&g_ao[(size_t)(b * SS + row1) * DM + col] = o1;
    }
    if (t == 0) {
        int gi0 = (b * NH + h) * SS + row0;
        int gi1 = (b * NH + h) * SS + row1;
        g_m[gi0] = deg0 ? -1e9f : m0;
        g_l[gi0] = deg0 ? (float)SS : l0;
        g_m[gi1] = deg1 ? -1e9f : m1;
        g_l[gi1] = deg1 ? (float)SS : l1;
    }
}

// ============================================================
// Optional second pass: full attention probabilities (unchanged)
// ============================================================
__global__ __launch_bounds__(256) void attn_write(
    const int* __restrict__ token_ids, float* __restrict__ attn)
{
    int kvb = blockIdx.x, qb = blockIdx.y;
    int bh = blockIdx.z;
    int b = bh >> 4, h = bh & 15;
    int q0 = qb * 64, kv0 = kvb * 64;
    int tid = threadIdx.x;
    int tx = tid & 15, ty = tid >> 4;

    if (kv0 > q0 + 63) {
#pragma unroll
        for (int i = 0; i < 4; i++) {
            int q = q0 + ty * 4 + i;
            int gi = (b * NH + h) * SS + q;
            float m = g_m[gi];
            float val = (m <= -1e8f) ? (1.f / g_l[gi]) : 0.f;
            float4 o = { val, val, val, val };
            *(float4*)&attn[((size_t)(b * NH + h) * SS + q) * SS + kv0 + tx * 4] = o;
        }
        return;
    }

    __shared__ float Qs[64][65];
    __shared__ float Ks2[64][65];
    __shared__ int padf[64];
    {
        int r = tid >> 2;
        int d0 = (tid & 3) * 16;
        const float* qp = &g_q[(size_t)(b * SS + q0 + r) * DM + h * DK + d0];
        const float* kp = &g_k[(size_t)(b * SS + kv0 + r) * DM + h * DK + d0];
#pragma unroll
        for (int i = 0; i < 16; i += 4) {
            float4 v4 = *(const float4*)(qp + i);
            Qs[d0 + i + 0][r] = v4.x; Qs[d0 + i + 1][r] = v4.y;
            Qs[d0 + i + 2][r] = v4.z; Qs[d0 + i + 3][r] = v4.w;
            float4 k4 = *(const float4*)(kp + i);
            Ks2[d0 + i + 0][r] = k4.x; Ks2[d0 + i + 1][r] = k4.y;
            Ks2[d0 + i + 2][r] = k4.z; Ks2[d0 + i + 3][r] = k4.w;
        }
    }
    if (tid < 64) padf[tid] = (token_ids[b * SS + kv0 + tid] == 0);
    __syncthreads();

    float s[4][4];
#pragma unroll
    for (int i = 0; i < 4; i++)
#pragma unroll
        for (int j = 0; j < 4; j++) s[i][j] = 0.f;
#pragma unroll
    for (int kk = 0; kk < 64; kk++) {
        float qv[4], kv_[4];
#pragma unroll
        for (int i = 0; i < 4; i++) qv[i] = Qs[kk][ty * 4 + i];
#pragma unroll
        for (int j = 0; j < 4; j++) kv_[j] = Ks2[kk][tx * 4 + j];
#pragma unroll
        for (int i = 0; i < 4; i++)
#pragma unroll
            for (int j = 0; j < 4; j++)
                s[i][j] = fmaf(qv[i], kv_[j], s[i][j]);
    }
#pragma unroll
    for (int i = 0; i < 4; i++) {
        int q = q0 + ty * 4 + i;
        int gi = (b * NH + h) * SS + q;
        float m = g_m[gi];
        float invl = 1.f / g_l[gi];
        float4 o;
        float ov[4];
#pragma unroll
        for (int j = 0; j < 4; j++) {
            int kvi = kv0 + tx * 4 + j;
            float v = s[i][j] * 0.125f;
            if (kvi > q || padf[tx * 4 + j]) v = -1e9f;
            ov[j] = __expf(v - m) * invl;
        }
        o.x = ov[0]; o.y = ov[1]; o.z = ov[2]; o.w = ov[3];
        *(float4*)&attn[((size_t)(b * NH + h) * SS + q) * SS + kv0 + tx * 4] = o;
    }
}

// ============================================================
extern "C" void kernel_launch(void* const* d_in, const int* in_sizes, int n_in,
                              void* d_out, int out_size)
{
    const float* x  = (const float*)d_in[0];
    const int*  tok = (const int*)d_in[1];
    const float* wq = (const float*)d_in[2];
    const float* bq = (const float*)d_in[3];
    const float* wk = (const float*)d_in[4];
    const float* bk = (const float*)d_in[5];
    const float* wv = (const float*)d_in[6];
    const float* bv = (const float*)d_in[7];
    const float* wo = (const float*)d_in[8];
    const float* bo = (const float*)d_in[9];
    float* out = (float*)d_out;

    dim3 gT(DM / 32, DM / 32), bT(32, 8);
    dim3 gG(DM / 128, NR / 128);

    split_bf16<<<1024, 256>>>(x, 0);                   // x -> g_xh/g_xl

    transpose_split<<<gT, bT>>>(wq);
    gemm_bf16split<<<gG, 256>>>(0, bq, nullptr, 1);    // -> g_q
    transpose_split<<<gT, bT>>>(wk);
    gemm_bf16split<<<gG, 256>>>(0, bk, nullptr, 2);    // -> g_k
    transpose_split<<<gT, bT>>>(wv);
    gemm_bf16split<<<gG, 256>>>(0, bv, nullptr, 3);    // -> g_v

    flash_tc<<<dim3(SS / 64, NH, BB), 128>>>(tok);

    bool want_out  = (out_size != ATTN_ELEMS);
    bool want_attn = (out_size >= ATTN_ELEMS);
    float* attn_ptr = nullptr;
    if (out_size == ATTN_ELEMS) attn_ptr = out;
    else if (out_size >= OUT_ELEMS + ATTN_ELEMS) attn_ptr = out + OUT_ELEMS;

    if (want_out) {
        split_bf16<<<1024, 256>>>(nullptr, 1);         // g_ao -> g_aoh/g_aol
        transpose_split<<<gT, bT>>>(wo);
        gemm_bf16split<<<gG, 256>>>(1, bo, out, 0);    // -> out
    }
    if (want_attn && attn_ptr)
        attn_write<<<dim3(SS / 64, SS / 64, BB * NH), 256>>>(tok, attn_ptr);
}

// round 6
// speedup vs baseline: 1.6469x; 1.0436x over previous
#include <cuda_runtime.h>
#include <cuda_bf16.h>
#include <math.h>
#include <stdint.h>

#define BB 2
#define SS 2048
#define DM 1024
#define NH 16
#define DK 64
#define NR (BB*SS)          // 4096 rows
#define OUT_ELEMS (NR*DM)               // 4194304
#define ATTN_ELEMS (BB*NH*SS*SS)        // 134217728

// ---- scratch (device globals; no allocation allowed) ----
__device__ float g_q[NR*DM];
__device__ float g_k[NR*DM];
__device__ float g_v[NR*DM];
__device__ float g_ao[NR*DM];
__device__ float g_m[BB*NH*SS];
__device__ float g_l[BB*NH*SS];
// bf16 split operands
__device__ __nv_bfloat16 g_xh[NR*DM],  g_xl[NR*DM];      // input x split
__device__ __nv_bfloat16 g_aoh[NR*DM], g_aol[NR*DM];     // attn output split
__device__ __nv_bfloat16 g_wth[3*DM*DM], g_wtl[3*DM*DM]; // weights, transposed [N][K] (up to 3 fused)

__device__ __forceinline__ uint32_t smem_u32(const void* p) {
    uint32_t a;
    asm("{ .reg .u64 t; cvta.to.shared.u64 t, %1; cvt.u32.u64 %0, t; }" : "=r"(a) : "l"(p));
    return a;
}
#define CP_ASYNC16(dst, src) \
    asm volatile("cp.async.cg.shared.global [%0], [%1], 16;" :: "r"(dst), "l"(src))
#define CP_COMMIT() asm volatile("cp.async.commit_group;" ::: "memory")
#define CP_WAIT(n)  asm volatile("cp.async.wait_group %0;" :: "n"(n) : "memory")

__device__ __forceinline__ void mma16816(float c[4], const unsigned a[4], const unsigned b[2])
{
    asm volatile(
        "mma.sync.aligned.m16n8k16.row.col.f32.bf16.bf16.f32 "
        "{%0,%1,%2,%3}, {%4,%5,%6,%7}, {%8,%9}, {%0,%1,%2,%3};\n"
        : "+f"(c[0]), "+f"(c[1]), "+f"(c[2]), "+f"(c[3])
        : "r"(a[0]), "r"(a[1]), "r"(a[2]), "r"(a[3]), "r"(b[0]), "r"(b[1]));
}
__device__ __forceinline__ unsigned pack_bf2(__nv_bfloat16 a, __nv_bfloat16 b)
{
    return (unsigned)__bfloat16_as_ushort(a) | ((unsigned)__bfloat16_as_ushort(b) << 16);
}

// ============================================================
// split fp32 -> (bf16 hi, bf16 lo).  sel: 0 = x, 1 = g_ao
// ============================================================
__global__ __launch_bounds__(256) void split_bf16(const float* __restrict__ src_ext, int sel)
{
    const float* src = sel ? g_ao : src_ext;
    __nv_bfloat16* hi = sel ? g_aoh : g_xh;
    __nv_bfloat16* lo = sel ? g_aol : g_xl;
    int n = NR * DM;
    for (int i = blockIdx.x * blockDim.x + threadIdx.x; i < n; i += gridDim.x * blockDim.x) {
        float v = src[i];
        __nv_bfloat16 h = __float2bfloat16(v);
        hi[i] = h;
        lo[i] = __float2bfloat16(v - __bfloat162float(h));
    }
}

// ============================================================
// batched transpose + split: w[z] [K][N] fp32 -> g_wth/g_wtl + z*DM*DM  [N][K]
// ============================================================
__global__ __launch_bounds__(256) void transpose_split3(
    const float* __restrict__ w0, const float* __restrict__ w1, const float* __restrict__ w2)
{
    __shared__ float tile[32][33];
    int z = blockIdx.z;
    const float* w = (z == 0) ? w0 : (z == 1 ? w1 : w2);
    size_t wo = (size_t)z * DM * DM;
    int tx = threadIdx.x, ty = threadIdx.y;       // block 32 x 8
    int n0 = blockIdx.x * 32, k0 = blockIdx.y * 32;
#pragma unroll
    for (int j = 0; j < 32; j += 8)
        tile[ty + j][tx] = w[(size_t)(k0 + ty + j) * DM + n0 + tx];
    __syncthreads();
#pragma unroll
    for (int j = 0; j < 32; j += 8) {
        float v = tile[tx][ty + j];
        __nv_bfloat16 h = __float2bfloat16(v);
        size_t o = wo + (size_t)(n0 + ty + j) * DM + k0 + tx;
        g_wth[o] = h;
        g_wtl[o] = __float2bfloat16(v - __bfloat162float(h));
    }
}

// ============================================================
// split-bf16 tensor-core GEMM, cp.async 2-stage pipeline.
// C[M,N] = (Ah+Al)@(Wh+Wl)^T + bias ; 128x128x32 tiles, 256 thr.
// qkv=1: blockIdx.x in [0,24): wsel = x>>3 selects weight/bias/output q/k/v.
// qkv=0: single GEMM, output C_ext, weight slot 0, bias0.
// ============================================================
#define TILE_B   10240            // 128 rows * 80 B (SPAD=40 bf16)
#define STAGE_B  (4*TILE_B)       // Ah,Al,Bh,Bl
#define GP_SMEM  (2*STAGE_B)      // 81920

__global__ __launch_bounds__(256) void gemm_pipe(
    int asel, const float* __restrict__ bias0, const float* __restrict__ bias1,
    const float* __restrict__ bias2, float* __restrict__ C_ext, int qkv)
{
    extern __shared__ char sm[];
    uint32_t sbase = smem_u32(sm);

    const __nv_bfloat16* Ah = asel ? g_aoh : g_xh;
    const __nv_bfloat16* Al = asel ? g_aol : g_xl;
    int wsel = qkv ? (blockIdx.x >> 3) : 0;
    int col0 = (qkv ? (blockIdx.x & 7) : blockIdx.x) * 128;
    float* C = qkv ? (wsel == 0 ? g_q : (wsel == 1 ? g_k : g_v)) : C_ext;
    const float* bias = (wsel == 0) ? bias0 : (wsel == 1 ? bias1 : bias2);
    const __nv_bfloat16* Wh = g_wth + (size_t)wsel * DM * DM;
    const __nv_bfloat16* Wl = g_wtl + (size_t)wsel * DM * DM;
    int row0 = blockIdx.y * 128;

    int tid = threadIdx.x;
    int lane = tid & 31, warp = tid >> 5;
    int wm = warp & 1, wn = warp >> 1;            // 2 x 4 warp grid
    int g = lane >> 2, t = lane & 3;

    float c[4][4][4];
#pragma unroll
    for (int i = 0; i < 4; i++)
#pragma unroll
        for (int j = 0; j < 4; j++)
#pragma unroll
            for (int r = 0; r < 4; r++) c[i][j][r] = 0.f;

    // loader mapping: row = tid>>1 (0..127), col-half = (tid&1)*16
    int lr = tid >> 1;
    int lco = (tid & 1) * 16;
    const __nv_bfloat16* pAh = &Ah[(size_t)(row0 + lr) * DM + lco];
    const __nv_bfloat16* pAl = &Al[(size_t)(row0 + lr) * DM + lco];
    const __nv_bfloat16* pBh = &Wh[(size_t)(col0 + lr) * DM + lco];
    const __nv_bfloat16* pBl = &Wl[(size_t)(col0 + lr) * DM + lco];
    uint32_t sA = sbase + lr * 80 + lco * 2;      // +0 tile offset

#define LOAD_STAGE(ch, st) do {                                              \
        int k0_ = (ch) * 32;                                                 \
        uint32_t d_ = sA + (st) * STAGE_B;                                   \
        CP_ASYNC16(d_,                pAh + k0_);                            \
        CP_ASYNC16(d_ + 16,           pAh + k0_ + 8);                        \
        CP_ASYNC16(d_ + TILE_B,       pAl + k0_);                            \
        CP_ASYNC16(d_ + TILE_B + 16,  pAl + k0_ + 8);                        \
        CP_ASYNC16(d_ + 2*TILE_B,     pBh + k0_);                            \
        CP_ASYNC16(d_ + 2*TILE_B+16,  pBh + k0_ + 8);                        \
        CP_ASYNC16(d_ + 3*TILE_B,     pBl + k0_);                            \
        CP_ASYNC16(d_ + 3*TILE_B+16,  pBl + k0_ + 8);                        \
    } while (0)

#define SMA(st, tile, rr, cc) \
    (*(const unsigned*)(sm + (st) * STAGE_B + (tile) * TILE_B + (rr) * 80 + (cc) * 2))

    const int NCH = DM / 32;   // 32
    LOAD_STAGE(0, 0);
    CP_COMMIT();

    for (int ch = 0; ch < NCH; ch++) {
        int st = ch & 1;
        if (ch + 1 < NCH) {
            LOAD_STAGE(ch + 1, (ch + 1) & 1);
            CP_COMMIT();
            CP_WAIT(1);
        } else {
            CP_WAIT(0);
        }
        __syncthreads();

#pragma unroll
        for (int kk = 0; kk < 32; kk += 16) {
            unsigned ah[4][4], al[4][4], bh[4][2], bl[4][2];
#pragma unroll
            for (int mt = 0; mt < 4; mt++) {
                int rb = wm * 64 + mt * 16;
                ah[mt][0] = SMA(st, 0, rb + g,     kk + 2 * t);
                ah[mt][1] = SMA(st, 0, rb + g + 8, kk + 2 * t);
                ah[mt][2] = SMA(st, 0, rb + g,     kk + 2 * t + 8);
                ah[mt][3] = SMA(st, 0, rb + g + 8, kk + 2 * t + 8);
                al[mt][0] = SMA(st, 1, rb + g,     kk + 2 * t);
                al[mt][1] = SMA(st, 1, rb + g + 8, kk + 2 * t);
                al[mt][2] = SMA(st, 1, rb + g,     kk + 2 * t + 8);
                al[mt][3] = SMA(st, 1, rb + g + 8, kk + 2 * t + 8);
            }
#pragma unroll
            for (int nt = 0; nt < 4; nt++) {
                int cb = wn * 32 + nt * 8;
                bh[nt][0] = SMA(st, 2, cb + g, kk + 2 * t);
                bh[nt][1] = SMA(st, 2, cb + g, kk + 2 * t + 8);
                bl[nt][0] = SMA(st, 3, cb + g, kk + 2 * t);
                bl[nt][1] = SMA(st, 3, cb + g, kk + 2 * t + 8);
            }
#pragma unroll
            for (int mt = 0; mt < 4; mt++)
#pragma unroll
                for (int nt = 0; nt < 4; nt++) {
                    mma16816(c[mt][nt], ah[mt], bh[nt]);
                    mma16816(c[mt][nt], ah[mt], bl[nt]);
                    mma16816(c[mt][nt], al[mt], bh[nt]);
                }
        }
        __syncthreads();
    }

    // epilogue: bias + store
#pragma unroll
    for (int mt = 0; mt < 4; mt++) {
#pragma unroll
        for (int nt = 0; nt < 4; nt++) {
            int col = col0 + wn * 32 + nt * 8 + 2 * t;
            float bx = bias[col], by = bias[col + 1];
            int r0 = row0 + wm * 64 + mt * 16 + g;
            float2 o0 = { c[mt][nt][0] + bx, c[mt][nt][1] + by };
            float2 o1 = { c[mt][nt][2] + bx, c[mt][nt][3] + by };
            *(float2*)&C[(size_t)r0 * DM + col] = o0;
            *(float2*)&C[(size_t)(r0 + 8) * DM + col] = o1;
        }
    }
}

// ============================================================
// Tensor-core flash attention (unchanged from R4 pass)
// ============================================================
__global__ __launch_bounds__(128) void flash_tc(const int* __restrict__ token_ids)
{
    __shared__ __nv_bfloat16 Qh[64][72], Ql[64][72];
    __shared__ __nv_bfloat16 Kh[32][72], Kl[32][72];
    __shared__ __nv_bfloat16 Vth[64][40], Vtl[64][40];
    __shared__ int padf[32];

    int qb = blockIdx.x, h = blockIdx.y, b = blockIdx.z;
    int q0 = qb * 64;
    int tid = threadIdx.x, lane = tid & 31, w = tid >> 5;
    int g = lane >> 2, t = lane & 3;

    {
        int r = tid >> 1, c0 = (tid & 1) * 32;
        const float* qp = &g_q[(size_t)(b * SS + q0 + r) * DM + h * DK + c0];
#pragma unroll
        for (int i = 0; i < 32; i += 2) {
            float2 v = *(const float2*)(qp + i);
            __nv_bfloat16 h0 = __float2bfloat16(v.x), h1 = __float2bfloat16(v.y);
            __nv_bfloat16 l0 = __float2bfloat16(v.x - __bfloat162float(h0));
            __nv_bfloat16 l1 = __float2bfloat16(v.y - __bfloat162float(h1));
            *(unsigned*)&Qh[r][c0 + i] = pack_bf2(h0, h1);
            *(unsigned*)&Ql[r][c0 + i] = pack_bf2(l0, l1);
        }
    }

    float o[8][4];
#pragma unroll
    for (int i = 0; i < 8; i++)
#pragma unroll
        for (int j = 0; j < 4; j++) o[i][j] = 0.f;
    float m0 = -INFINITY, m1 = -INFINITY, l0 = 0.f, l1 = 0.f;

    int row0 = q0 + w * 16 + g;
    int row1 = row0 + 8;

    int kb_max = 2 * qb + 1;
    for (int kb = 0; kb <= kb_max; kb++) {
        int kv0 = kb * 32;
        {
            int r = tid >> 2, c0 = (tid & 3) * 16;
            const float* kp = &g_k[(size_t)(b * SS + kv0 + r) * DM + h * DK + c0];
            const float* vp = &g_v[(size_t)(b * SS + kv0 + r) * DM + h * DK + c0];
#pragma unroll
            for (int i = 0; i < 16; i += 2) {
                float2 kv2 = *(const float2*)(kp + i);
                __nv_bfloat16 h0 = __float2bfloat16(kv2.x), h1 = __float2bfloat16(kv2.y);
                __nv_bfloat16 q0b = __float2bfloat16(kv2.x - __bfloat162float(h0));
                __nv_bfloat16 q1b = __float2bfloat16(kv2.y - __bfloat162float(h1));
                *(unsigned*)&Kh[r][c0 + i] = pack_bf2(h0, h1);
                *(unsigned*)&Kl[r][c0 + i] = pack_bf2(q0b, q1b);
                float2 vv2 = *(const float2*)(vp + i);
                __nv_bfloat16 vh0 = __float2bfloat16(vv2.x), vh1 = __float2bfloat16(vv2.y);
                Vth[c0 + i][r] = vh0;
                Vth[c0 + i + 1][r] = vh1;
                Vtl[c0 + i][r] = __float2bfloat16(vv2.x - __bfloat162float(vh0));
                Vtl[c0 + i + 1][r] = __float2bfloat16(vv2.y - __bfloat162float(vh1));
            }
        }
        if (tid < 32) padf[tid] = (token_ids[b * SS + kv0 + tid] == 0);
        __syncthreads();

        float s[4][4];
#pragma unroll
        for (int nt = 0; nt < 4; nt++)
#pragma unroll
            for (int r = 0; r < 4; r++) s[nt][r] = 0.f;

#pragma unroll
        for (int kc = 0; kc < 4; kc++) {
            int kk = kc * 16;
            unsigned aqh[4], aql[4];
            int rb = w * 16;
            aqh[0] = *(const unsigned*)&Qh[rb + g][kk + 2 * t];
            aqh[1] = *(const unsigned*)&Qh[rb + g + 8][kk + 2 * t];
            aqh[2] = *(const unsigned*)&Qh[rb + g][kk + 2 * t + 8];
            aqh[3] = *(const unsigned*)&Qh[rb + g + 8][kk + 2 * t + 8];
            aql[0] = *(const unsigned*)&Ql[rb + g][kk + 2 * t];
            aql[1] = *(const unsigned*)&Ql[rb + g + 8][kk + 2 * t];
            aql[2] = *(const unsigned*)&Ql[rb + g][kk + 2 * t + 8];
            aql[3] = *(const unsigned*)&Ql[rb + g + 8][kk + 2 * t + 8];
#pragma unroll
            for (int nt = 0; nt < 4; nt++) {
                unsigned bh[2], bl[2];
                bh[0] = *(const unsigned*)&Kh[nt * 8 + g][kk + 2 * t];
                bh[1] = *(const unsigned*)&Kh[nt * 8 + g][kk + 2 * t + 8];
                bl[0] = *(const unsigned*)&Kl[nt * 8 + g][kk + 2 * t];
                bl[1] = *(const unsigned*)&Kl[nt * 8 + g][kk + 2 * t + 8];
                mma16816(s[nt], aqh, bh);
                mma16816(s[nt], aqh, bl);
                mma16816(s[nt], aql, bh);
            }
        }

#pragma unroll
        for (int nt = 0; nt < 4; nt++) {
            int c0 = nt * 8 + 2 * t;
            int k0i = kv0 + c0, k1i = k0i + 1;
            int p0 = padf[c0], p1 = padf[c0 + 1];
            float v0 = s[nt][0] * 0.125f, v1 = s[nt][1] * 0.125f;
            float v2 = s[nt][2] * 0.125f, v3 = s[nt][3] * 0.125f;
            s[nt][0] = (k0i > row0 || p0) ? -1e9f : v0;
            s[nt][1] = (k1i > row0 || p1) ? -1e9f : v1;
            s[nt][2] = (k0i > row1 || p0) ? -1e9f : v2;
            s[nt][3] = (k1i > row1 || p1) ? -1e9f : v3;
        }

        float rmax0 = -INFINITY, rmax1 = -INFINITY;
#pragma unroll
        for (int nt = 0; nt < 4; nt++) {
            rmax0 = fmaxf(rmax0, fmaxf(s[nt][0], s[nt][1]));
            rmax1 = fmaxf(rmax1, fmaxf(s[nt][2], s[nt][3]));
        }
#pragma unroll
        for (int off = 1; off <= 2; off <<= 1) {
            rmax0 = fmaxf(rmax0, __shfl_xor_sync(0xffffffffu, rmax0, off));
            rmax1 = fmaxf(rmax1, __shfl_xor_sync(0xffffffffu, rmax1, off));
        }
        float mn0 = fmaxf(m0, rmax0), mn1 = fmaxf(m1, rmax1);

        float rs0 = 0.f, rs1 = 0.f;
#pragma unroll
        for (int nt = 0; nt < 4; nt++) {
            s[nt][0] = __expf(s[nt][0] - mn0);
            s[nt][1] = __expf(s[nt][1] - mn0);
            s[nt][2] = __expf(s[nt][2] - mn1);
            s[nt][3] = __expf(s[nt][3] - mn1);
            rs0 += s[nt][0] + s[nt][1];
            rs1 += s[nt][2] + s[nt][3];
        }
#pragma unroll
        for (int off = 1; off <= 2; off <<= 1) {
            rs0 += __shfl_xor_sync(0xffffffffu, rs0, off);
            rs1 += __shfl_xor_sync(0xffffffffu, rs1, off);
        }
        float sc0 = __expf(m0 - mn0), sc1 = __expf(m1 - mn1);
        l0 = l0 * sc0 + rs0;
        l1 = l1 * sc1 + rs1;
        m0 = mn0; m1 = mn1;
#pragma unroll
        for (int ot = 0; ot < 8; ot++) {
            o[ot][0] *= sc0; o[ot][1] *= sc0;
            o[ot][2] *= sc1; o[ot][3] *= sc1;
        }

#pragma unroll
        for (int kc = 0; kc < 2; kc++) {
            unsigned ph[4], pl[4];
            {
                int n0i = 2 * kc, n1i = 2 * kc + 1;
                __nv_bfloat16 h00 = __float2bfloat16(s[n0i][0]);
                __nv_bfloat16 h01 = __float2bfloat16(s[n0i][1]);
                __nv_bfloat16 h02 = __float2bfloat16(s[n0i][2]);
                __nv_bfloat16 h03 = __float2bfloat16(s[n0i][3]);
                __nv_bfloat16 h10 = __float2bfloat16(s[n1i][0]);
                __nv_bfloat16 h11 = __float2bfloat16(s[n1i][1]);
                __nv_bfloat16 h12 = __float2bfloat16(s[n1i][2]);
                __nv_bfloat16 h13 = __float2bfloat16(s[n1i][3]);
                ph[0] = pack_bf2(h00, h01);
                ph[1] = pack_bf2(h02, h03);
                ph[2] = pack_bf2(h10, h11);
                ph[3] = pack_bf2(h12, h13);
                pl[0] = pack_bf2(__float2bfloat16(s[n0i][0] - __bfloat162float(h00)),
                                 __float2bfloat16(s[n0i][1] - __bfloat162float(h01)));
                pl[1] = pack_bf2(__float2bfloat16(s[n0i][2] - __bfloat162float(h02)),
                                 __float2bfloat16(s[n0i][3] - __bfloat162float(h03)));
                pl[2] = pack_bf2(__float2bfloat16(s[n1i][0] - __bfloat162float(h10)),
                                 __float2bfloat16(s[n1i][1] - __bfloat162float(h11)));
                pl[3] = pack_bf2(__float2bfloat16(s[n1i][2] - __bfloat162float(h12)),
                                 __float2bfloat16(s[n1i][3] - __bfloat162float(h13)));
            }
            int kk = kc * 16;
#pragma unroll
            for (int ot = 0; ot < 8; ot++) {
                unsigned bvh[2], bvl[2];
                bvh[0] = *(const unsigned*)&Vth[ot * 8 + g][kk + 2 * t];
                bvh[1] = *(const unsigned*)&Vth[ot * 8 + g][kk + 2 * t + 8];
                bvl[0] = *(const unsigned*)&Vtl[ot * 8 + g][kk + 2 * t];
                bvl[1] = *(const unsigned*)&Vtl[ot * 8 + g][kk + 2 * t + 8];
                mma16816(o[ot], ph, bvh);
                mma16816(o[ot], ph, bvl);
                mma16816(o[ot], pl, bvh);
            }
        }
        __syncthreads();
    }

    bool deg0 = !(m0 > -1e8f);
    bool deg1 = !(m1 > -1e8f);
    float inv0 = deg0 ? 0.f : 1.f / l0;
    float inv1 = deg1 ? 0.f : 1.f / l1;
#pragma unroll
    for (int ot = 0; ot < 8; ot++) {
        int col = h * DK + ot * 8 + 2 * t;
        float2 o0 = { o[ot][0] * inv0, o[ot][1] * inv0 };
        float2 o1 = { o[ot][2] * inv1, o[ot][3] * inv1 };
        if (deg0) {
            float s0 = 0.f, s1 = 0.f;
            const float* vp = &g_v[(size_t)(b * SS) * DM + col];
            for (int kv = 0; kv < SS; kv++) {
                float2 v2 = *(const float2*)(vp + (size_t)kv * DM);
                s0 += v2.x; s1 += v2.y;
            }
            o0.x = s0 / SS; o0.y = s1 / SS;
        }
        if (deg1) {
            float s0 = 0.f, s1 = 0.f;
            const float* vp = &g_v[(size_t)(b * SS) * DM + col];
            for (int kv = 0; kv < SS; kv++) {
                float2 v2 = *(const float2*)(vp + (size_t)kv * DM);
                s0 += v2.x; s1 += v2.y;
            }
            o1.x = s0 / SS; o1.y = s1 / SS;
        }
        *(float2*)&g_ao[(size_t)(b * SS + row0) * DM + col] = o0;
        *(float2*)&g_ao[(size_t)(b * SS + row1) * DM + col] = o1;
    }
    if (t == 0) {
        int gi0 = (b * NH + h) * SS + row0;
        int gi1 = (b * NH + h) * SS + row1;
        g_m[gi0] = deg0 ? -1e9f : m0;
        g_l[gi0] = deg0 ? (float)SS : l0;
        g_m[gi1] = deg1 ? -1e9f : m1;
        g_l[gi1] = deg1 ? (float)SS : l1;
    }
}

// ============================================================
// Optional second pass: full attention probabilities (unchanged)
// ============================================================
__global__ __launch_bounds__(256) void attn_write(
    const int* __restrict__ token_ids, float* __restrict__ attn)
{
    int kvb = blockIdx.x, qb = blockIdx.y;
    int bh = blockIdx.z;
    int b = bh >> 4, h = bh & 15;
    int q0 = qb * 64, kv0 = kvb * 64;
    int tid = threadIdx.x;
    int tx = tid & 15, ty = tid >> 4;

    if (kv0 > q0 + 63) {
#pragma unroll
        for (int i = 0; i < 4; i++) {
            int q = q0 + ty * 4 + i;
            int gi = (b * NH + h) * SS + q;
            float m = g_m[gi];
            float val = (m <= -1e8f) ? (1.f / g_l[gi]) : 0.f;
            float4 o = { val, val, val, val };
            *(float4*)&attn[((size_t)(b * NH + h) * SS + q) * SS + kv0 + tx * 4] = o;
        }
        return;
    }

    __shared__ float Qs[64][65];
    __shared__ float Ks2[64][65];
    __shared__ int padf[64];
    {
        int r = tid >> 2;
        int d0 = (tid & 3) * 16;
        const float* qp = &g_q[(size_t)(b * SS + q0 + r) * DM + h * DK + d0];
        const float* kp = &g_k[(size_t)(b * SS + kv0 + r) * DM + h * DK + d0];
#pragma unroll
        for (int i = 0; i < 16; i += 4) {
            float4 v4 = *(const float4*)(qp + i);
            Qs[d0 + i + 0][r] = v4.x; Qs[d0 + i + 1][r] = v4.y;
            Qs[d0 + i + 2][r] = v4.z; Qs[d0 + i + 3][r] = v4.w;
            float4 k4 = *(const float4*)(kp + i);
            Ks2[d0 + i + 0][r] = k4.x; Ks2[d0 + i + 1][r] = k4.y;
            Ks2[d0 + i + 2][r] = k4.z; Ks2[d0 + i + 3][r] = k4.w;
        }
    }
    if (tid < 64) padf[tid] = (token_ids[b * SS + kv0 + tid] == 0);
    __syncthreads();

    float s[4][4];
#pragma unroll
    for (int i = 0; i < 4; i++)
#pragma unroll
        for (int j = 0; j < 4; j++) s[i][j] = 0.f;
#pragma unroll
    for (int kk = 0; kk < 64; kk++) {
        float qv[4], kv_[4];
#pragma unroll
        for (int i = 0; i < 4; i++) qv[i] = Qs[kk][ty * 4 + i];
#pragma unroll
        for (int j = 0; j < 4; j++) kv_[j] = Ks2[kk][tx * 4 + j];
#pragma unroll
        for (int i = 0; i < 4; i++)
#pragma unroll
            for (int j = 0; j < 4; j++)
                s[i][j] = fmaf(qv[i], kv_[j], s[i][j]);
    }
#pragma unroll
    for (int i = 0; i < 4; i++) {
        int q = q0 + ty * 4 + i;
        int gi = (b * NH + h) * SS + q;
        float m = g_m[gi];
        float invl = 1.f / g_l[gi];
        float4 o;
        float ov[4];
#pragma unroll
        for (int j = 0; j < 4; j++) {
            int kvi = kv0 + tx * 4 + j;
            float v = s[i][j] * 0.125f;
            if (kvi > q || padf[tx * 4 + j]) v = -1e9f;
            ov[j] = __expf(v - m) * invl;
        }
        o.x = ov[0]; o.y = ov[1]; o.z = ov[2]; o.w = ov[3];
        *(float4*)&attn[((size_t)(b * NH + h) * SS + q) * SS + kv0 + tx * 4] = o;
    }
}

// ============================================================
extern "C" void kernel_launch(void* const* d_in, const int* in_sizes, int n_in,
                              void* d_out, int out_size)
{
    const float* x  = (const float*)d_in[0];
    const int*  tok = (const int*)d_in[1];
    const float* wq = (const float*)d_in[2];
    const float* bq = (const float*)d_in[3];
    const float* wk = (const float*)d_in[4];
    const float* bk = (const float*)d_in[5];
    const float* wv = (const float*)d_in[6];
    const float* bv = (const float*)d_in[7];
    const float* wo = (const float*)d_in[8];
    const float* bo = (const float*)d_in[9];
    float* out = (float*)d_out;

    cudaFuncSetAttribute(gemm_pipe, cudaFuncAttributeMaxDynamicSharedMemorySize, GP_SMEM);

    dim3 bT(32, 8);

    split_bf16<<<1024, 256>>>(x, 0);                               // x -> g_xh/g_xl
    transpose_split3<<<dim3(32, 32, 3), bT>>>(wq, wk, wv);         // weights -> slots 0,1,2
    gemm_pipe<<<dim3(24, 32), 256, GP_SMEM>>>(0, bq, bk, bv, nullptr, 1);  // fused QKV

    flash_tc<<<dim3(SS / 64, NH, BB), 128>>>(tok);

    bool want_out  = (out_size != ATTN_ELEMS);
    bool want_attn = (out_size >= ATTN_ELEMS);
    float* attn_ptr = nullptr;
    if (out_size == ATTN_ELEMS) attn_ptr = out;
    else if (out_size >= OUT_ELEMS + ATTN_ELEMS) attn_ptr = out + OUT_ELEMS;

    if (want_out) {
        split_bf16<<<1024, 256>>>(nullptr, 1);                     // g_ao -> g_aoh/g_aol
        transpose_split3<<<dim3(32, 32, 1), bT>>>(wo, wo, wo);     // wo -> slot 0
        gemm_pipe<<<dim3(8, 32), 256, GP_SMEM>>>(1, bo, bo, bo, out, 0);
    }
    if (want_attn && attn_ptr)
        attn_write<<<dim3(SS / 64, SS / 64, BB * NH), 256>>>(tok, attn_ptr);
}

// round 7
// speedup vs baseline: 1.8239x; 1.1075x over previous
#include <cuda_runtime.h>
#include <cuda_bf16.h>
#include <math.h>
#include <stdint.h>

#define BB 2
#define SS 2048
#define DM 1024
#define NH 16
#define DK 64
#define NR (BB*SS)          // 4096 rows
#define OUT_ELEMS (NR*DM)               // 4194304
#define ATTN_ELEMS (BB*NH*SS*SS)        // 134217728

// ---- scratch (device globals; no allocation allowed) ----
__device__ float g_q[NR*DM];
__device__ float g_k[NR*DM];
__device__ float g_v[NR*DM];
__device__ float g_m[BB*NH*SS];
__device__ float g_l[BB*NH*SS];
// bf16 split operands
__device__ __nv_bfloat16 g_xh[NR*DM],  g_xl[NR*DM];      // input x split
__device__ __nv_bfloat16 g_aoh[NR*DM], g_aol[NR*DM];     // attn output split (written by flash)
__device__ __nv_bfloat16 g_wth[3*DM*DM], g_wtl[3*DM*DM]; // weights, transposed [N][K]
// bf16 split Q/K/V (written by GEMM epilogue, read by flash)
__device__ __nv_bfloat16 g_qh[NR*DM], g_ql[NR*DM];
__device__ __nv_bfloat16 g_kh[NR*DM], g_kl[NR*DM];
__device__ __nv_bfloat16 g_vh[NR*DM], g_vl[NR*DM];

__device__ __forceinline__ uint32_t smem_u32(const void* p) {
    uint32_t a;
    asm("{ .reg .u64 t; cvta.to.shared.u64 t, %1; cvt.u32.u64 %0, t; }" : "=r"(a) : "l"(p));
    return a;
}
#define CP_ASYNC16(dst, src) \
    asm volatile("cp.async.cg.shared.global [%0], [%1], 16;" :: "r"(dst), "l"(src))
#define CP_COMMIT() asm volatile("cp.async.commit_group;" ::: "memory")
#define CP_WAIT(n)  asm volatile("cp.async.wait_group %0;" :: "n"(n) : "memory")

__device__ __forceinline__ void mma16816(float c[4], const unsigned a[4], const unsigned b[2])
{
    asm volatile(
        "mma.sync.aligned.m16n8k16.row.col.f32.bf16.bf16.f32 "
        "{%0,%1,%2,%3}, {%4,%5,%6,%7}, {%8,%9}, {%0,%1,%2,%3};\n"
        : "+f"(c[0]), "+f"(c[1]), "+f"(c[2]), "+f"(c[3])
        : "r"(a[0]), "r"(a[1]), "r"(a[2]), "r"(a[3]), "r"(b[0]), "r"(b[1]));
}
__device__ __forceinline__ unsigned pack_bf2(__nv_bfloat16 a, __nv_bfloat16 b)
{
    return (unsigned)__bfloat16_as_ushort(a) | ((unsigned)__bfloat16_as_ushort(b) << 16);
}
__device__ __forceinline__ unsigned split_hi2(float x, float y)
{
    return pack_bf2(__float2bfloat16(x), __float2bfloat16(y));
}
__device__ __forceinline__ unsigned split_lo2(float x, float y)
{
    __nv_bfloat16 hx = __float2bfloat16(x), hy = __float2bfloat16(y);
    return pack_bf2(__float2bfloat16(x - __bfloat162float(hx)),
                    __float2bfloat16(y - __bfloat162float(hy)));
}

// ============================================================
// split fp32 -> (bf16 hi, bf16 lo): x only
// ============================================================
__global__ __launch_bounds__(256) void split_bf16(const float* __restrict__ src)
{
    int n = NR * DM;
    for (int i = blockIdx.x * blockDim.x + threadIdx.x; i < n; i += gridDim.x * blockDim.x) {
        float v = src[i];
        __nv_bfloat16 h = __float2bfloat16(v);
        g_xh[i] = h;
        g_xl[i] = __float2bfloat16(v - __bfloat162float(h));
    }
}

// ============================================================
// batched transpose + split: w[z] [K][N] fp32 -> slot z [N][K]
// ============================================================
__global__ __launch_bounds__(256) void transpose_split3(
    const float* __restrict__ w0, const float* __restrict__ w1, const float* __restrict__ w2)
{
    __shared__ float tile[32][33];
    int z = blockIdx.z;
    const float* w = (z == 0) ? w0 : (z == 1 ? w1 : w2);
    size_t wo = (size_t)z * DM * DM;
    int tx = threadIdx.x, ty = threadIdx.y;
    int n0 = blockIdx.x * 32, k0 = blockIdx.y * 32;
#pragma unroll
    for (int j = 0; j < 32; j += 8)
        tile[ty + j][tx] = w[(size_t)(k0 + ty + j) * DM + n0 + tx];
    __syncthreads();
#pragma unroll
    for (int j = 0; j < 32; j += 8) {
        float v = tile[tx][ty + j];
        __nv_bfloat16 h = __float2bfloat16(v);
        size_t o = wo + (size_t)(n0 + ty + j) * DM + k0 + tx;
        g_wth[o] = h;
        g_wtl[o] = __float2bfloat16(v - __bfloat162float(h));
    }
}

// ============================================================
// split-bf16 tensor-core GEMM, cp.async 2-stage pipeline.
// qkv=1: fused QKV; epilogue also writes bf16 hi/lo q/k/v.
// ============================================================
#define TILE_B   10240            // 128 rows * 80 B
#define STAGE_B  (4*TILE_B)
#define GP_SMEM  (2*STAGE_B)      // 81920

__global__ __launch_bounds__(256) void gemm_pipe(
    int asel, const float* __restrict__ bias0, const float* __restrict__ bias1,
    const float* __restrict__ bias2, float* __restrict__ C_ext, int qkv)
{
    extern __shared__ char sm[];
    uint32_t sbase = smem_u32(sm);

    const __nv_bfloat16* Ah = asel ? g_aoh : g_xh;
    const __nv_bfloat16* Al = asel ? g_aol : g_xl;
    int wsel = qkv ? (blockIdx.x >> 3) : 0;
    int col0 = (qkv ? (blockIdx.x & 7) : blockIdx.x) * 128;
    float* C = qkv ? (wsel == 0 ? g_q : (wsel == 1 ? g_k : g_v)) : C_ext;
    __nv_bfloat16* Ch = nullptr; __nv_bfloat16* Cl = nullptr;
    if (qkv) {
        Ch = (wsel == 0) ? g_qh : (wsel == 1 ? g_kh : g_vh);
        Cl = (wsel == 0) ? g_ql : (wsel == 1 ? g_kl : g_vl);
    }
    const float* bias = (wsel == 0) ? bias0 : (wsel == 1 ? bias1 : bias2);
    const __nv_bfloat16* Wh = g_wth + (size_t)wsel * DM * DM;
    const __nv_bfloat16* Wl = g_wtl + (size_t)wsel * DM * DM;
    int row0 = blockIdx.y * 128;

    int tid = threadIdx.x;
    int lane = tid & 31, warp = tid >> 5;
    int wm = warp & 1, wn = warp >> 1;
    int g = lane >> 2, t = lane & 3;

    float c[4][4][4];
#pragma unroll
    for (int i = 0; i < 4; i++)
#pragma unroll
        for (int j = 0; j < 4; j++)
#pragma unroll
            for (int r = 0; r < 4; r++) c[i][j][r] = 0.f;

    int lr = tid >> 1;
    int lco = (tid & 1) * 16;
    const __nv_bfloat16* pAh = &Ah[(size_t)(row0 + lr) * DM + lco];
    const __nv_bfloat16* pAl = &Al[(size_t)(row0 + lr) * DM + lco];
    const __nv_bfloat16* pBh = &Wh[(size_t)(col0 + lr) * DM + lco];
    const __nv_bfloat16* pBl = &Wl[(size_t)(col0 + lr) * DM + lco];
    uint32_t sA = sbase + lr * 80 + lco * 2;

#define LOAD_STAGE(ch, st) do {                                              \
        int k0_ = (ch) * 32;                                                 \
        uint32_t d_ = sA + (st) * STAGE_B;                                   \
        CP_ASYNC16(d_,                pAh + k0_);                            \
        CP_ASYNC16(d_ + 16,           pAh + k0_ + 8);                        \
        CP_ASYNC16(d_ + TILE_B,       pAl + k0_);                            \
        CP_ASYNC16(d_ + TILE_B + 16,  pAl + k0_ + 8);                        \
        CP_ASYNC16(d_ + 2*TILE_B,     pBh + k0_);                            \
        CP_ASYNC16(d_ + 2*TILE_B+16,  pBh + k0_ + 8);                        \
        CP_ASYNC16(d_ + 3*TILE_B,     pBl + k0_);                            \
        CP_ASYNC16(d_ + 3*TILE_B+16,  pBl + k0_ + 8);                        \
    } while (0)

#define SMA(st, tile, rr, cc) \
    (*(const unsigned*)(sm + (st) * STAGE_B + (tile) * TILE_B + (rr) * 80 + (cc) * 2))

    const int NCH = DM / 32;
    LOAD_STAGE(0, 0);
    CP_COMMIT();

    for (int ch = 0; ch < NCH; ch++) {
        int st = ch & 1;
        if (ch + 1 < NCH) {
            LOAD_STAGE(ch + 1, (ch + 1) & 1);
            CP_COMMIT();
            CP_WAIT(1);
        } else {
            CP_WAIT(0);
        }
        __syncthreads();

#pragma unroll
        for (int kk = 0; kk < 32; kk += 16) {
            unsigned ah[4][4], al[4][4], bh[4][2], bl[4][2];
#pragma unroll
            for (int mt = 0; mt < 4; mt++) {
                int rb = wm * 64 + mt * 16;
                ah[mt][0] = SMA(st, 0, rb + g,     kk + 2 * t);
                ah[mt][1] = SMA(st, 0, rb + g + 8, kk + 2 * t);
                ah[mt][2] = SMA(st, 0, rb + g,     kk + 2 * t + 8);
                ah[mt][3] = SMA(st, 0, rb + g + 8, kk + 2 * t + 8);
                al[mt][0] = SMA(st, 1, rb + g,     kk + 2 * t);
                al[mt][1] = SMA(st, 1, rb + g + 8, kk + 2 * t);
                al[mt][2] = SMA(st, 1, rb + g,     kk + 2 * t + 8);
                al[mt][3] = SMA(st, 1, rb + g + 8, kk + 2 * t + 8);
            }
#pragma unroll
            for (int nt = 0; nt < 4; nt++) {
                int cb = wn * 32 + nt * 8;
                bh[nt][0] = SMA(st, 2, cb + g, kk + 2 * t);
                bh[nt][1] = SMA(st, 2, cb + g, kk + 2 * t + 8);
                bl[nt][0] = SMA(st, 3, cb + g, kk + 2 * t);
                bl[nt][1] = SMA(st, 3, cb + g, kk + 2 * t + 8);
            }
#pragma unroll
            for (int mt = 0; mt < 4; mt++)
#pragma unroll
                for (int nt = 0; nt < 4; nt++) {
                    mma16816(c[mt][nt], ah[mt], bh[nt]);
                    mma16816(c[mt][nt], ah[mt], bl[nt]);
                    mma16816(c[mt][nt], al[mt], bh[nt]);
                }
        }
        __syncthreads();
    }

#pragma unroll
    for (int mt = 0; mt < 4; mt++) {
#pragma unroll
        for (int nt = 0; nt < 4; nt++) {
            int col = col0 + wn * 32 + nt * 8 + 2 * t;
            float bx = bias[col], by = bias[col + 1];
            int r0 = row0 + wm * 64 + mt * 16 + g;
            float2 o0 = { c[mt][nt][0] + bx, c[mt][nt][1] + by };
            float2 o1 = { c[mt][nt][2] + bx, c[mt][nt][3] + by };
            *(float2*)&C[(size_t)r0 * DM + col] = o0;
            *(float2*)&C[(size_t)(r0 + 8) * DM + col] = o1;
            if (qkv) {
                *(unsigned*)&Ch[(size_t)r0 * DM + col]       = split_hi2(o0.x, o0.y);
                *(unsigned*)&Cl[(size_t)r0 * DM + col]       = split_lo2(o0.x, o0.y);
                *(unsigned*)&Ch[(size_t)(r0 + 8) * DM + col] = split_hi2(o1.x, o1.y);
                *(unsigned*)&Cl[(size_t)(r0 + 8) * DM + col] = split_lo2(o1.x, o1.y);
            }
        }
    }
}

// ============================================================
// Flash attention v2: BQ=128, BKV=32, 256 thr (8 warps x 16 rows).
// Reads pre-split bf16 q/k/v; writes pre-split bf16 ao.
// ============================================================
#define FQH 0
#define FQL 18432
#define FKH 36864
#define FKL 41472
#define FVH 46080
#define FVL 51200
#define FPAD 56320
#define F_SMEM 56448

#define QHF(r, c)  (*(const unsigned*)(sm + FQH + (r) * 144 + (c) * 2))
#define QLF(r, c)  (*(const unsigned*)(sm + FQL + (r) * 144 + (c) * 2))
#define KHF(r, c)  (*(const unsigned*)(sm + FKH + (r) * 144 + (c) * 2))
#define KLF(r, c)  (*(const unsigned*)(sm + FKL + (r) * 144 + (c) * 2))
#define VTHF(d, k) (*(const unsigned*)(sm + FVH + (d) * 80 + (k) * 2))
#define VTLF(d, k) (*(const unsigned*)(sm + FVL + (d) * 80 + (k) * 2))

__global__ __launch_bounds__(256) void flash_tc2(const int* __restrict__ token_ids)
{
    extern __shared__ char sm[];
    int* padf = (int*)(sm + FPAD);

    int qb = blockIdx.x, h = blockIdx.y, b = blockIdx.z;
    int q0 = qb * 128;
    int tid = threadIdx.x, lane = tid & 31, w = tid >> 5;
    int g = lane >> 2, t = lane & 3;

    // Q tile fill: 128 rows x 64 bf16, hi+lo
    {
        int r = tid >> 1, c0 = (tid & 1) * 32;
        const uint4* ph = (const uint4*)&g_qh[(size_t)(b * SS + q0 + r) * DM + h * DK + c0];
        const uint4* pl = (const uint4*)&g_ql[(size_t)(b * SS + q0 + r) * DM + h * DK + c0];
#pragma unroll
        for (int j = 0; j < 4; j++) {
            *(uint4*)(sm + FQH + r * 144 + c0 * 2 + j * 16) = ph[j];
            *(uint4*)(sm + FQL + r * 144 + c0 * 2 + j * 16) = pl[j];
        }
    }

    float o[8][4];
#pragma unroll
    for (int i = 0; i < 8; i++)
#pragma unroll
        for (int j = 0; j < 4; j++) o[i][j] = 0.f;
    float m0 = -INFINITY, m1 = -INFINITY, l0 = 0.f, l1 = 0.f;

    int row0 = q0 + w * 16 + g;
    int row1 = row0 + 8;

    int kb_max = 4 * qb + 3;
    for (int kb = 0; kb <= kb_max; kb++) {
        int kv0 = kb * 32;
        if (tid < 128) {        // K tile: 32 x 64 hi+lo
            int r = tid >> 2, c0 = (tid & 3) * 16;
            size_t gi = (size_t)(b * SS + kv0 + r) * DM + h * DK + c0;
            const uint4* ph = (const uint4*)&g_kh[gi];
            const uint4* pl = (const uint4*)&g_kl[gi];
            *(uint4*)(sm + FKH + r * 144 + c0 * 2)      = ph[0];
            *(uint4*)(sm + FKH + r * 144 + c0 * 2 + 16) = ph[1];
            *(uint4*)(sm + FKL + r * 144 + c0 * 2)      = pl[0];
            *(uint4*)(sm + FKL + r * 144 + c0 * 2 + 16) = pl[1];
        } else {                // V tile transposed: Vt[64][32]
            int t2 = tid - 128;
            int r = t2 >> 2, c0 = (t2 & 3) * 16;
            size_t gi = (size_t)(b * SS + kv0 + r) * DM + h * DK + c0;
            __nv_bfloat16 vh[16], vl[16];
            *(uint4*)&vh[0] = ((const uint4*)&g_vh[gi])[0];
            *(uint4*)&vh[8] = ((const uint4*)&g_vh[gi])[1];
            *(uint4*)&vl[0] = ((const uint4*)&g_vl[gi])[0];
            *(uint4*)&vl[8] = ((const uint4*)&g_vl[gi])[1];
#pragma unroll
            for (int i = 0; i < 16; i++) {
                *(__nv_bfloat16*)(sm + FVH + (c0 + i) * 80 + r * 2) = vh[i];
                *(__nv_bfloat16*)(sm + FVL + (c0 + i) * 80 + r * 2) = vl[i];
            }
        }
        if (tid < 32) padf[tid] = (token_ids[b * SS + kv0 + tid] == 0);
        __syncthreads();

        // S = Q K^T : per warp 16x32
        float s[4][4];
#pragma unroll
        for (int nt = 0; nt < 4; nt++)
#pragma unroll
            for (int r = 0; r < 4; r++) s[nt][r] = 0.f;

        int rb = w * 16;
#pragma unroll
        for (int kc = 0; kc < 4; kc++) {
            int kk = kc * 16;
            unsigned aqh[4], aql[4];
            aqh[0] = QHF(rb + g,     kk + 2 * t);
            aqh[1] = QHF(rb + g + 8, kk + 2 * t);
            aqh[2] = QHF(rb + g,     kk + 2 * t + 8);
            aqh[3] = QHF(rb + g + 8, kk + 2 * t + 8);
            aql[0] = QLF(rb + g,     kk + 2 * t);
            aql[1] = QLF(rb + g + 8, kk + 2 * t);
            aql[2] = QLF(rb + g,     kk + 2 * t + 8);
            aql[3] = QLF(rb + g + 8, kk + 2 * t + 8);
#pragma unroll
            for (int nt = 0; nt < 4; nt++) {
                unsigned bh[2], bl[2];
                bh[0] = KHF(nt * 8 + g, kk + 2 * t);
                bh[1] = KHF(nt * 8 + g, kk + 2 * t + 8);
                bl[0] = KLF(nt * 8 + g, kk + 2 * t);
                bl[1] = KLF(nt * 8 + g, kk + 2 * t + 8);
                mma16816(s[nt], aqh, bh);
                mma16816(s[nt], aqh, bl);
                mma16816(s[nt], aql, bh);
            }
        }

        // scale + mask
#pragma unroll
        for (int nt = 0; nt < 4; nt++) {
            int c0 = nt * 8 + 2 * t;
            int k0i = kv0 + c0, k1i = k0i + 1;
            int p0 = padf[c0], p1 = padf[c0 + 1];
            float v0 = s[nt][0] * 0.125f, v1 = s[nt][1] * 0.125f;
            float v2 = s[nt][2] * 0.125f, v3 = s[nt][3] * 0.125f;
            s[nt][0] = (k0i > row0 || p0) ? -1e9f : v0;
            s[nt][1] = (k1i > row0 || p1) ? -1e9f : v1;
            s[nt][2] = (k0i > row1 || p0) ? -1e9f : v2;
            s[nt][3] = (k1i > row1 || p1) ? -1e9f : v3;
        }

        float rmax0 = -INFINITY, rmax1 = -INFINITY;
#pragma unroll
        for (int nt = 0; nt < 4; nt++) {
            rmax0 = fmaxf(rmax0, fmaxf(s[nt][0], s[nt][1]));
            rmax1 = fmaxf(rmax1, fmaxf(s[nt][2], s[nt][3]));
        }
#pragma unroll
        for (int off = 1; off <= 2; off <<= 1) {
            rmax0 = fmaxf(rmax0, __shfl_xor_sync(0xffffffffu, rmax0, off));
            rmax1 = fmaxf(rmax1, __shfl_xor_sync(0xffffffffu, rmax1, off));
        }
        float mn0 = fmaxf(m0, rmax0), mn1 = fmaxf(m1, rmax1);

        float rs0 = 0.f, rs1 = 0.f;
#pragma unroll
        for (int nt = 0; nt < 4; nt++) {
            s[nt][0] = __expf(s[nt][0] - mn0);
            s[nt][1] = __expf(s[nt][1] - mn0);
            s[nt][2] = __expf(s[nt][2] - mn1);
            s[nt][3] = __expf(s[nt][3] - mn1);
            rs0 += s[nt][0] + s[nt][1];
            rs1 += s[nt][2] + s[nt][3];
        }
#pragma unroll
        for (int off = 1; off <= 2; off <<= 1) {
            rs0 += __shfl_xor_sync(0xffffffffu, rs0, off);
            rs1 += __shfl_xor_sync(0xffffffffu, rs1, off);
        }
        float sc0 = __expf(m0 - mn0), sc1 = __expf(m1 - mn1);
        l0 = l0 * sc0 + rs0;
        l1 = l1 * sc1 + rs1;
        m0 = mn0; m1 = mn1;
#pragma unroll
        for (int ot = 0; ot < 8; ot++) {
            o[ot][0] *= sc0; o[ot][1] *= sc0;
            o[ot][2] *= sc1; o[ot][3] *= sc1;
        }

        // P fragments directly from S regs
#pragma unroll
        for (int kc = 0; kc < 2; kc++) {
            unsigned ph[4], pl[4];
            {
                int n0i = 2 * kc, n1i = 2 * kc + 1;
                ph[0] = split_hi2(s[n0i][0], s[n0i][1]);
                ph[1] = split_hi2(s[n0i][2], s[n0i][3]);
                ph[2] = split_hi2(s[n1i][0], s[n1i][1]);
                ph[3] = split_hi2(s[n1i][2], s[n1i][3]);
                pl[0] = split_lo2(s[n0i][0], s[n0i][1]);
                pl[1] = split_lo2(s[n0i][2], s[n0i][3]);
                pl[2] = split_lo2(s[n1i][0], s[n1i][1]);
                pl[3] = split_lo2(s[n1i][2], s[n1i][3]);
            }
            int kk = kc * 16;
#pragma unroll
            for (int ot = 0; ot < 8; ot++) {
                unsigned bvh[2], bvl[2];
                bvh[0] = VTHF(ot * 8 + g, kk + 2 * t);
                bvh[1] = VTHF(ot * 8 + g, kk + 2 * t + 8);
                bvl[0] = VTLF(ot * 8 + g, kk + 2 * t);
                bvl[1] = VTLF(ot * 8 + g, kk + 2 * t + 8);
                mma16816(o[ot], ph, bvh);
                mma16816(o[ot], ph, bvl);
                mma16816(o[ot], pl, bvh);
            }
        }
        __syncthreads();
    }

    bool deg0 = !(m0 > -1e8f);
    bool deg1 = !(m1 > -1e8f);
    float inv0 = deg0 ? 0.f : 1.f / l0;
    float inv1 = deg1 ? 0.f : 1.f / l1;
#pragma unroll
    for (int ot = 0; ot < 8; ot++) {
        int col = h * DK + ot * 8 + 2 * t;
        float2 o0 = { o[ot][0] * inv0, o[ot][1] * inv0 };
        float2 o1 = { o[ot][2] * inv1, o[ot][3] * inv1 };
        if (deg0) {
            float s0 = 0.f, s1 = 0.f;
            const float* vp = &g_v[(size_t)(b * SS) * DM + col];
            for (int kv = 0; kv < SS; kv++) {
                float2 v2 = *(const float2*)(vp + (size_t)kv * DM);
                s0 += v2.x; s1 += v2.y;
            }
            o0.x = s0 / SS; o0.y = s1 / SS;
        }
        if (deg1) {
            float s0 = 0.f, s1 = 0.f;
            const float* vp = &g_v[(size_t)(b * SS) * DM + col];
            for (int kv = 0; kv < SS; kv++) {
                float2 v2 = *(const float2*)(vp + (size_t)kv * DM);
                s0 += v2.x; s1 += v2.y;
            }
            o1.x = s0 / SS; o1.y = s1 / SS;
        }
        *(unsigned*)&g_aoh[(size_t)(b * SS + row0) * DM + col] = split_hi2(o0.x, o0.y);
        *(unsigned*)&g_aol[(size_t)(b * SS + row0) * DM + col] = split_lo2(o0.x, o0.y);
        *(unsigned*)&g_aoh[(size_t)(b * SS + row1) * DM + col] = split_hi2(o1.x, o1.y);
        *(unsigned*)&g_aol[(size_t)(b * SS + row1) * DM + col] = split_lo2(o1.x, o1.y);
    }
    if (t == 0) {
        int gi0 = (b * NH + h) * SS + row0;
        int gi1 = (b * NH + h) * SS + row1;
        g_m[gi0] = deg0 ? -1e9f : m0;
        g_l[gi0] = deg0 ? (float)SS : l0;
        g_m[gi1] = deg1 ? -1e9f : m1;
        g_l[gi1] = deg1 ? (float)SS : l1;
    }
}

// ============================================================
// Optional second pass: full attention probabilities
// ============================================================
__global__ __launch_bounds__(256) void attn_write(
    const int* __restrict__ token_ids, float* __restrict__ attn)
{
    int kvb = blockIdx.x, qb = blockIdx.y;
    int bh = blockIdx.z;
    int b = bh >> 4, h = bh & 15;
    int q0 = qb * 64, kv0 = kvb * 64;
    int tid = threadIdx.x;
    int tx = tid & 15, ty = tid >> 4;

    if (kv0 > q0 + 63) {
#pragma unroll
        for (int i = 0; i < 4; i++) {
            int q = q0 + ty * 4 + i;
            int gi = (b * NH + h) * SS + q;
            float m = g_m[gi];
            float val = (m <= -1e8f) ? (1.f / g_l[gi]) : 0.f;
            float4 o = { val, val, val, val };
            *(float4*)&attn[((size_t)(b * NH + h) * SS + q) * SS + kv0 + tx * 4] = o;
        }
        return;
    }

    __shared__ float Qs[64][65];
    __shared__ float Ks2[64][65];
    __shared__ int padf[64];
    {
        int r = tid >> 2;
        int d0 = (tid & 3) * 16;
        const float* qp = &g_q[(size_t)(b * SS + q0 + r) * DM + h * DK + d0];
        const float* kp = &g_k[(size_t)(b * SS + kv0 + r) * DM + h * DK + d0];
#pragma unroll
        for (int i = 0; i < 16; i += 4) {
            float4 v4 = *(const float4*)(qp + i);
            Qs[d0 + i + 0][r] = v4.x; Qs[d0 + i + 1][r] = v4.y;
            Qs[d0 + i + 2][r] = v4.z; Qs[d0 + i + 3][r] = v4.w;
            float4 k4 = *(const float4*)(kp + i);
            Ks2[d0 + i + 0][r] = k4.x; Ks2[d0 + i + 1][r] = k4.y;
            Ks2[d0 + i + 2][r] = k4.z; Ks2[d0 + i + 3][r] = k4.w;
        }
    }
    if (tid < 64) padf[tid] = (token_ids[b * SS + kv0 + tid] == 0);
    __syncthreads();

    float s[4][4];
#pragma unroll
    for (int i = 0; i < 4; i++)
#pragma unroll
        for (int j = 0; j < 4; j++) s[i][j] = 0.f;
#pragma unroll
    for (int kk = 0; kk < 64; kk++) {
        float qv[4], kv_[4];
#pragma unroll
        for (int i = 0; i < 4; i++) qv[i] = Qs[kk][ty * 4 + i];
#pragma unroll
        for (int j = 0; j < 4; j++) kv_[j] = Ks2[kk][tx * 4 + j];
#pragma unroll
        for (int i = 0; i < 4; i++)
#pragma unroll
            for (int j = 0; j < 4; j++)
                s[i][j] = fmaf(qv[i], kv_[j], s[i][j]);
    }
#pragma unroll
    for (int i = 0; i < 4; i++) {
        int q = q0 + ty * 4 + i;
        int gi = (b * NH + h) * SS + q;
        float m = g_m[gi];
        float invl = 1.f / g_l[gi];
        float4 o;
        float ov[4];
#pragma unroll
        for (int j = 0; j < 4; j++) {
            int kvi = kv0 + tx * 4 + j;
            float v = s[i][j] * 0.125f;
            if (kvi > q || padf[tx * 4 + j]) v = -1e9f;
            ov[j] = __expf(v - m) * invl;
        }
        o.x = ov[0]; o.y = ov[1]; o.z = ov[2]; o.w = ov[3];
        *(float4*)&attn[((size_t)(b * NH + h) * SS + q) * SS + kv0 + tx * 4] = o;
    }
}

// ============================================================
extern "C" void kernel_launch(void* const* d_in, const int* in_sizes, int n_in,
                              void* d_out, int out_size)
{
    const float* x  = (const float*)d_in[0];
    const int*  tok = (const int*)d_in[1];
    const float* wq = (const float*)d_in[2];
    const float* bq = (const float*)d_in[3];
    const float* wk = (const float*)d_in[4];
    const float* bk = (const float*)d_in[5];
    const float* wv = (const float*)d_in[6];
    const float* bv = (const float*)d_in[7];
    const float* wo = (const float*)d_in[8];
    const float* bo = (const float*)d_in[9];
    float* out = (float*)d_out;

    cudaFuncSetAttribute(gemm_pipe, cudaFuncAttributeMaxDynamicSharedMemorySize, GP_SMEM);
    cudaFuncSetAttribute(flash_tc2, cudaFuncAttributeMaxDynamicSharedMemorySize, F_SMEM);

    dim3 bT(32, 8);

    split_bf16<<<1024, 256>>>(x);                                  // x -> g_xh/g_xl
    transpose_split3<<<dim3(32, 32, 3), bT>>>(wq, wk, wv);
    gemm_pipe<<<dim3(24, 32), 256, GP_SMEM>>>(0, bq, bk, bv, nullptr, 1);  // fused QKV + bf16 split out

    flash_tc2<<<dim3(SS / 128, NH, BB), 256, F_SMEM>>>(tok);

    bool want_out  = (out_size != ATTN_ELEMS);
    bool want_attn = (out_size >= ATTN_ELEMS);
    float* attn_ptr = nullptr;
    if (out_size == ATTN_ELEMS) attn_ptr = out;
    else if (out_size >= OUT_ELEMS + ATTN_ELEMS) attn_ptr = out + OUT_ELEMS;

    if (want_out) {
        transpose_split3<<<dim3(32, 32, 1), bT>>>(wo, wo, wo);
        gemm_pipe<<<dim3(8, 32), 256, GP_SMEM>>>(1, bo, bo, bo, out, 0);
    }
    if (want_attn && attn_ptr)
        attn_write<<<dim3(SS / 64, SS / 64, BB * NH), 256>>>(tok, attn_ptr);
}